// round 1
// baseline (speedup 1.0000x reference)
#include <cuda_runtime.h>
#include <math.h>

#define S      64
#define NSUB   1024
#define ESUB   16384
#define NGLOB  65536
#define EGLOB  1048576
#define F      128
#define KPOOL  512
#define NCLS   64

// ---------------- scratch (device globals; no allocation allowed) ----------------
__device__ float g_h    [S*NSUB*F];
__device__ float g_x1   [S*NSUB*F];
__device__ float g_x2   [S*NSUB*F];
__device__ float g_deg  [S*NSUB];        // deg -> dinv in place
__device__ float g_hp   [S*NSUB];
__device__ float g_score[S*NSUB];
__device__ int   g_sel  [S*KPOOL];
__device__ int   g_pos  [S*NSUB];
__device__ float g_xpool[S*KPOOL*F];
__device__ float g_hpool[S*KPOOL*F];
__device__ float g_deg2 [S*KPOOL];
__device__ float g_xsub [S*KPOOL*F];
__device__ float g_subemb[S*256];
__device__ float g_v    [S*256];
__device__ float g_att  [S*256];
__device__ float g_gemb [NGLOB*384];     // 100 MB
__device__ float g_hf   [NGLOB*64];
__device__ float g_degf [NGLOB];
__device__ float g_agg  [NGLOB*64];

// ---------------- utility kernels ----------------
__global__ void k_fill(float* p, float v, int n) {
    int i = blockIdx.x * blockDim.x + threadIdx.x;
    if (i < n) p[i] = v;
}
__global__ void k_rsqrt(float* p, int n) {
    int i = blockIdx.x * blockDim.x + threadIdx.x;
    if (i < n) p[i] = rsqrtf(p[i]);
}
__global__ void k_relu(float* p, int n) {
    int i = blockIdx.x * blockDim.x + threadIdx.x;
    if (i < n) p[i] = fmaxf(p[i], 0.f);
}
__global__ void k_copy4(const float4* __restrict__ src, float4* __restrict__ dst, int n4) {
    int i = blockIdx.x * blockDim.x + threadIdx.x;
    if (i < n4) dst[i] = src[i];
}

// ---------------- SGEMM: C[M,Nc] = A[M,K] @ B[K,Nc] (fp32, 128-row tiles) ----------------
template<int BN, int TN>
__global__ void sgemm(const float* __restrict__ A, const float* __restrict__ B,
                      float* __restrict__ C, int M, int Kd, int Nc) {
    __shared__ float As[8][132];
    __shared__ float Bs[8][BN];
    int tid = threadIdx.x;               // 256 threads
    int tx = tid & 15, ty = tid >> 4;    // 16 x 16
    int bx = blockIdx.x, by = blockIdx.y;
    const float* Ab = A + (size_t)by * 128 * Kd;
    const float* Bb = B + bx * BN;
    float acc[8][TN];
    #pragma unroll
    for (int i = 0; i < 8; i++)
        #pragma unroll
        for (int j = 0; j < TN; j++) acc[i][j] = 0.f;

    int arow = tid >> 1, acol = (tid & 1) * 4;
    for (int k0 = 0; k0 < Kd; k0 += 8) {
        float4 av = *(const float4*)(Ab + (size_t)arow * Kd + k0 + acol);
        As[acol + 0][arow] = av.x; As[acol + 1][arow] = av.y;
        As[acol + 2][arow] = av.z; As[acol + 3][arow] = av.w;
        if (BN == 128) {
            int brow = tid >> 5, bcol = (tid & 31) * 4;
            *(float4*)&Bs[brow][bcol] = *(const float4*)(Bb + (size_t)(k0 + brow) * Nc + bcol);
        } else {
            if (tid < 128) {
                int brow = tid >> 4, bcol = (tid & 15) * 4;
                *(float4*)&Bs[brow][bcol] = *(const float4*)(Bb + (size_t)(k0 + brow) * Nc + bcol);
            }
        }
        __syncthreads();
        #pragma unroll
        for (int k = 0; k < 8; k++) {
            float a[8], b[TN];
            #pragma unroll
            for (int i = 0; i < 8; i++)  a[i] = As[k][ty * 8 + i];
            #pragma unroll
            for (int j = 0; j < TN; j++) b[j] = Bs[k][tx * TN + j];
            #pragma unroll
            for (int i = 0; i < 8; i++)
                #pragma unroll
                for (int j = 0; j < TN; j++)
                    acc[i][j] += a[i] * b[j];
        }
        __syncthreads();
    }
    #pragma unroll
    for (int i = 0; i < 8; i++)
        #pragma unroll
        for (int j = 0; j < TN; j++)
            C[(size_t)(by * 128 + ty * 8 + i) * Nc + bx * BN + tx * TN + j] = acc[i][j];
}

// ---------------- degree kernels ----------------
__global__ void k_deg_sub(const int* __restrict__ sei) {
    int e = blockIdx.x * blockDim.x + threadIdx.x;
    if (e >= S * ESUB) return;
    int s = e / ESUB, j = e - s * ESUB;
    int dst = sei[s * 2 * ESUB + ESUB + j];
    atomicAdd(&g_deg[s * NSUB + dst], 1.f);
}
__global__ void k_deg_pool(const int* __restrict__ sei) {
    int e = blockIdx.x * blockDim.x + threadIdx.x;
    if (e >= S * ESUB) return;
    int s = e / ESUB, j = e - s * ESUB;
    int src = sei[s * 2 * ESUB + j];
    int dst = sei[s * 2 * ESUB + ESUB + j];
    int ps = g_pos[s * NSUB + src], pd = g_pos[s * NSUB + dst];
    if (ps >= 0 && pd >= 0) atomicAdd(&g_deg2[s * KPOOL + pd], 1.f);
}
__global__ void k_deg_glob(const int* __restrict__ eidx) {
    int e = blockIdx.x * blockDim.x + threadIdx.x;
    if (e >= EGLOB) return;
    atomicAdd(&g_degf[eidx[EGLOB + e]], 1.f);
}

// ---------------- GCN init: out = h*dinv^2 + bias ----------------
__global__ void k_gcn_init(const float* __restrict__ h, const float* __restrict__ dinv,
                           const float* __restrict__ bias, float* __restrict__ out,
                           int rows, int fdim) {
    int i = blockIdx.x * blockDim.x + threadIdx.x;
    if (i >= rows * fdim) return;
    int r = i / fdim, c = i - r * fdim;
    float d = dinv[r];
    out[i] = h[i] * d * d + bias[c];
}

// ---------------- edge aggregation (warp per edge, F=128) ----------------
__global__ void k_edge_agg128(const int* __restrict__ sei, const float* __restrict__ h,
                              const float* __restrict__ dinv, float* __restrict__ out) {
    int w = (blockIdx.x * blockDim.x + threadIdx.x) >> 5;
    int lane = threadIdx.x & 31;
    if (w >= S * ESUB) return;
    int s = w / ESUB, e = w - s * ESUB;
    const int* base = sei + s * 2 * ESUB;
    int src = base[e], dst = base[ESUB + e];
    float c = dinv[s * NSUB + src] * dinv[s * NSUB + dst];
    float4 vv = ((const float4*)(h + (size_t)(s * NSUB + src) * F))[lane];
    float* od = out + (size_t)(s * NSUB + dst) * F + lane * 4;
    atomicAdd(od + 0, vv.x * c); atomicAdd(od + 1, vv.y * c);
    atomicAdd(od + 2, vv.z * c); atomicAdd(od + 3, vv.w * c);
}
__global__ void k_edge_agg_pool(const int* __restrict__ sei, const float* __restrict__ h,
                                const float* __restrict__ dinv, float* __restrict__ out) {
    int w = (blockIdx.x * blockDim.x + threadIdx.x) >> 5;
    int lane = threadIdx.x & 31;
    if (w >= S * ESUB) return;
    int s = w / ESUB, e = w - s * ESUB;
    const int* base = sei + s * 2 * ESUB;
    int src = base[e], dst = base[ESUB + e];
    int ps = g_pos[s * NSUB + src], pd = g_pos[s * NSUB + dst];
    if (ps < 0 || pd < 0) return;
    float c = dinv[s * KPOOL + ps] * dinv[s * KPOOL + pd];
    float4 vv = ((const float4*)(h + (size_t)(s * KPOOL + ps) * F))[lane];
    float* od = out + (size_t)(s * KPOOL + pd) * F + lane * 4;
    atomicAdd(od + 0, vv.x * c); atomicAdd(od + 1, vv.y * c);
    atomicAdd(od + 2, vv.z * c); atomicAdd(od + 3, vv.w * c);
}
// scalar edge agg for the scorer
__global__ void k_edge_agg1(const int* __restrict__ sei, const float* __restrict__ hp,
                            const float* __restrict__ dinv, float* __restrict__ out) {
    int e = blockIdx.x * blockDim.x + threadIdx.x;
    if (e >= S * ESUB) return;
    int s = e / ESUB, j = e - s * ESUB;
    const int* base = sei + s * 2 * ESUB;
    int src = base[j], dst = base[ESUB + j];
    float c = dinv[s * NSUB + src] * dinv[s * NSUB + dst];
    atomicAdd(&out[s * NSUB + dst], hp[s * NSUB + src] * c);
}
// final global graph edge agg (64 feats, warp per edge, float2 per lane)
__global__ void k_edge_agg_final(const int* __restrict__ eidx) {
    int w = (blockIdx.x * blockDim.x + threadIdx.x) >> 5;
    int lane = threadIdx.x & 31;
    if (w >= EGLOB) return;
    int src = eidx[w], dst = eidx[EGLOB + w];
    float c = g_degf[src] * g_degf[dst];
    float2 v = ((const float2*)(g_hf + (size_t)src * 64))[lane];
    float* od = g_agg + (size_t)dst * 64 + lane * 2;
    atomicAdd(od + 0, v.x * c); atomicAdd(od + 1, v.y * c);
}

// ---------------- scorer: hp = x1 @ Wp (dot per row) ----------------
__global__ void k_rowdot(const float* __restrict__ X, const float* __restrict__ w,
                         float* __restrict__ out, int rows) {
    int gw = (blockIdx.x * blockDim.x + threadIdx.x) >> 5;
    int lane = threadIdx.x & 31;
    if (gw >= rows) return;
    float4 x = ((const float4*)(X + (size_t)gw * F))[lane];
    float4 ww = ((const float4*)w)[lane];
    float acc = x.x * ww.x + x.y * ww.y + x.z * ww.z + x.w * ww.w;
    #pragma unroll
    for (int o = 16; o; o >>= 1) acc += __shfl_xor_sync(0xffffffffu, acc, o);
    if (lane == 0) out[gw] = acc;
}
__global__ void k_score_init(const float* __restrict__ hp, const float* __restrict__ dinv,
                             const float* __restrict__ bp, float* __restrict__ out) {
    int i = blockIdx.x * blockDim.x + threadIdx.x;
    if (i >= S * NSUB) return;
    float d = dinv[i];
    out[i] = hp[i] * d * d + bp[0];
}

// ---------------- top-512 of 1024 per subgraph (bitonic sort, value only) ----------------
__global__ void k_topk() {
    __shared__ float vals[1024];
    __shared__ int   idxs[1024];
    int s = blockIdx.x, t = threadIdx.x;  // 512 threads
    vals[t]       = g_score[s * NSUB + t];       idxs[t]       = t;
    vals[t + 512] = g_score[s * NSUB + t + 512]; idxs[t + 512] = t + 512;
    g_pos[s * NSUB + t] = -1;
    g_pos[s * NSUB + t + 512] = -1;
    __syncthreads();
    for (int k2 = 2; k2 <= 1024; k2 <<= 1) {
        for (int j = k2 >> 1; j > 0; j >>= 1) {
            int i = ((t & ~(j - 1)) << 1) | (t & (j - 1));
            int ixj = i | j;
            bool ascend = ((i & k2) != 0);
            float vi = vals[i], vj = vals[ixj];
            bool sw = ascend ? (vi > vj) : (vi < vj);
            if (sw) {
                vals[i] = vj; vals[ixj] = vi;
                int tmp = idxs[i]; idxs[i] = idxs[ixj]; idxs[ixj] = tmp;
            }
            __syncthreads();
        }
    }
    // descending: first 512 are top-K
    int selidx = idxs[t];
    g_sel[s * KPOOL + t] = selidx;
    g_pos[s * NSUB + selidx] = t;
}

// ---------------- x_pool = x1[sel] * tanh(score[sel]) ----------------
__global__ void k_xpool() {
    int i = blockIdx.x * blockDim.x + threadIdx.x;
    if (i >= S * KPOOL * F) return;
    int c = i & (F - 1);
    int rj = i >> 7;           // s*KPOOL + j
    int s = rj >> 9;           // /KPOOL
    int sel = g_sel[rj];
    float gate = tanhf(g_score[s * NSUB + sel]);
    g_xpool[i] = g_x1[(size_t)(s * NSUB + sel) * F + c] * gate;
}

// ---------------- subgraph embedding: max+mean over pooled rows ----------------
__global__ void k_emb() {
    int s = blockIdx.x, c = threadIdx.x;  // 128 threads
    float mx1 = -INFINITY, sm1 = 0.f, mx2 = -INFINITY, sm2 = 0.f;
    const float* xp = g_xpool + (size_t)s * KPOOL * F + c;
    const float* xs = g_xsub + (size_t)s * KPOOL * F + c;
    for (int j = 0; j < KPOOL; j++) {
        float v1 = xp[(size_t)j * F]; mx1 = fmaxf(mx1, v1); sm1 += v1;
        float v2 = xs[(size_t)j * F]; mx2 = fmaxf(mx2, v2); sm2 += v2;
    }
    g_subemb[s * 256 + c]       = mx1 + mx2;
    g_subemb[s * 256 + 128 + c] = sm1 * (1.f / KPOOL) + sm2 * (1.f / KPOOL);
}

// ---------------- small gemm: out[s,j] = X[s,:]@W[:,coloff+j] + b[coloff+j] ----------------
__global__ void k_small_gemm(const float* __restrict__ X, const float* __restrict__ W,
                             const float* __restrict__ b, float* __restrict__ out,
                             int ldw, int coloff, int Kd, int Ncols) {
    __shared__ float xs[256];
    int s = blockIdx.x;
    for (int i = threadIdx.x; i < Kd; i += blockDim.x) xs[i] = X[s * Kd + i];
    __syncthreads();
    int j = threadIdx.x;
    float acc = b[coloff + j];
    for (int k = 0; k < Kd; k++) acc += xs[k] * W[k * ldw + coloff + j];
    out[s * Ncols + j] = acc;
}

// ---------------- scatter combined -> global embedding ----------------
__global__ void k_scatter(const int* __restrict__ sorig) {
    int row = blockIdx.x;                // S*NSUB rows
    int c = threadIdx.x;                 // 384
    int s = row >> 10;
    int gi = sorig[row];
    float v = (c < F) ? g_x2[(size_t)row * F + c] : g_att[s * 256 + (c - F)];
    atomicAdd(&g_gemb[(size_t)gi * 384 + c], v);
}

// ---------------- log_softmax over 64 classes (warp per row) ----------------
__global__ void k_logsoftmax(float* __restrict__ out) {
    int gw = (blockIdx.x * blockDim.x + threadIdx.x) >> 5;
    int lane = threadIdx.x & 31;
    if (gw >= NGLOB) return;
    float a = g_agg[(size_t)gw * 64 + lane];
    float b = g_agg[(size_t)gw * 64 + 32 + lane];
    float m = fmaxf(a, b);
    #pragma unroll
    for (int o = 16; o; o >>= 1) m = fmaxf(m, __shfl_xor_sync(0xffffffffu, m, o));
    float ssum = expf(a - m) + expf(b - m);
    #pragma unroll
    for (int o = 16; o; o >>= 1) ssum += __shfl_xor_sync(0xffffffffu, ssum, o);
    float ls = m + logf(ssum);
    out[(size_t)gw * 64 + lane]      = a - ls;
    out[(size_t)gw * 64 + 32 + lane] = b - ls;
}

// ========================= host orchestration =========================
extern "C" void kernel_launch(void* const* d_in, const int* in_sizes, int n_in,
                              void* d_out, int out_size) {
    const float* sub_x = (const float*)d_in[0];
    const int*   sei   = (const int*)d_in[1];
    const int*   sorig = (const int*)d_in[2];
    const int*   eidx  = (const int*)d_in[3];
    const float* W1  = (const float*)d_in[4];
    const float* b1  = (const float*)d_in[5];
    const float* W2  = (const float*)d_in[6];
    const float* b2  = (const float*)d_in[7];
    const float* Wp  = (const float*)d_in[8];
    const float* bp  = (const float*)d_in[9];
    const float* Wsc = (const float*)d_in[10];
    const float* bsc = (const float*)d_in[11];
    const float* Wqkv= (const float*)d_in[12];
    const float* bqkv= (const float*)d_in[13];
    const float* Wo  = (const float*)d_in[14];
    const float* bo  = (const float*)d_in[15];
    const float* Wf  = (const float*)d_in[16];
    const float* bf  = (const float*)d_in[17];
    float* out = (float*)d_out;

    float *h, *x1, *x2, *deg, *hp, *score, *xpool, *hpool, *deg2, *xsub;
    float *subemb, *v, *att, *gemb, *hf, *degf, *agg;
    cudaGetSymbolAddress((void**)&h, g_h);
    cudaGetSymbolAddress((void**)&x1, g_x1);
    cudaGetSymbolAddress((void**)&x2, g_x2);
    cudaGetSymbolAddress((void**)&deg, g_deg);
    cudaGetSymbolAddress((void**)&hp, g_hp);
    cudaGetSymbolAddress((void**)&score, g_score);
    cudaGetSymbolAddress((void**)&xpool, g_xpool);
    cudaGetSymbolAddress((void**)&hpool, g_hpool);
    cudaGetSymbolAddress((void**)&deg2, g_deg2);
    cudaGetSymbolAddress((void**)&xsub, g_xsub);
    cudaGetSymbolAddress((void**)&subemb, g_subemb);
    cudaGetSymbolAddress((void**)&v, g_v);
    cudaGetSymbolAddress((void**)&att, g_att);
    cudaGetSymbolAddress((void**)&gemb, g_gemb);
    cudaGetSymbolAddress((void**)&hf, g_hf);
    cudaGetSymbolAddress((void**)&degf, g_degf);
    cudaGetSymbolAddress((void**)&agg, g_agg);

    const int T = 256;
    const int ROWS = S * NSUB;                 // 65536
    const int EDGES = S * ESUB;                // 1048576
    const int WARP_BLOCKS = EDGES / 8;         // 131072 (8 warps/block)

    // --- subgraph degrees / dinv ---
    k_fill<<<(ROWS + T - 1) / T, T>>>(deg, 1.f, ROWS);
    k_deg_sub<<<(EDGES + T - 1) / T, T>>>(sei);
    k_rsqrt<<<(ROWS + T - 1) / T, T>>>(deg, ROWS);

    // --- GCN1: x1 = relu(agg + h*d^2 + b1) ---
    sgemm<128, 8><<<dim3(1, ROWS / 128), 256>>>(sub_x, W1, h, ROWS, F, F);
    k_gcn_init<<<(ROWS * F + T - 1) / T, T>>>(h, deg, b1, x1, ROWS, F);
    k_edge_agg128<<<WARP_BLOCKS, 256>>>(sei, h, deg, x1);
    k_relu<<<(ROWS * F + T - 1) / T, T>>>(x1, ROWS * F);

    // --- GCN2: x2 ---
    sgemm<128, 8><<<dim3(1, ROWS / 128), 256>>>(x1, W2, h, ROWS, F, F);
    k_gcn_init<<<(ROWS * F + T - 1) / T, T>>>(h, deg, b2, x2, ROWS, F);
    k_edge_agg128<<<WARP_BLOCKS, 256>>>(sei, h, deg, x2);
    k_relu<<<(ROWS * F + T - 1) / T, T>>>(x2, ROWS * F);

    // --- scorer GCN (1 output dim) ---
    k_rowdot<<<(ROWS * 32 + T - 1) / T, T>>>(x1, Wp, hp, ROWS);
    k_score_init<<<(ROWS + T - 1) / T, T>>>(hp, deg, bp, score);
    k_edge_agg1<<<(EDGES + T - 1) / T, T>>>(sei, hp, deg, score);

    // --- top-k + pooling ---
    k_topk<<<S, 512>>>();
    k_xpool<<<(S * KPOOL * F + T - 1) / T, T>>>();

    // --- pooled graph degrees ---
    k_fill<<<(S * KPOOL + T - 1) / T, T>>>(deg2, 1.f, S * KPOOL);
    k_deg_pool<<<(EDGES + T - 1) / T, T>>>(sei);
    k_rsqrt<<<(S * KPOOL + T - 1) / T, T>>>(deg2, S * KPOOL);

    // --- pooled GCN: x_sub ---
    sgemm<128, 8><<<dim3(1, (S * KPOOL) / 128), 256>>>(xpool, Wsc, hpool, S * KPOOL, F, F);
    k_gcn_init<<<(S * KPOOL * F + T - 1) / T, T>>>(hpool, deg2, bsc, xsub, S * KPOOL, F);
    k_edge_agg_pool<<<WARP_BLOCKS, 256>>>(sei, hpool, deg2, xsub);
    k_relu<<<(S * KPOOL * F + T - 1) / T, T>>>(xsub, S * KPOOL * F);

    // --- subgraph embeddings + collapsed attention ---
    k_emb<<<S, 128>>>();
    k_small_gemm<<<S, 256>>>(subemb, Wqkv, bqkv, v, 768, 512, 256, 256);
    k_small_gemm<<<S, 256>>>(v, Wo, bo, att, 256, 0, 256, 256);

    // --- scatter into global embedding ---
    k_fill<<<(NGLOB * 384 + T - 1) / T, T>>>(gemb, 0.f, NGLOB * 384);
    k_scatter<<<ROWS, 384>>>(sorig);

    // --- global GCN + log_softmax ---
    k_fill<<<(NGLOB + T - 1) / T, T>>>(degf, 1.f, NGLOB);
    k_deg_glob<<<(EGLOB + T - 1) / T, T>>>(eidx);
    k_rsqrt<<<(NGLOB + T - 1) / T, T>>>(degf, NGLOB);

    sgemm<64, 4><<<dim3(1, NGLOB / 128), 256>>>(gemb, Wf, hf, NGLOB, 384, 64);
    k_gcn_init<<<(NGLOB * 64 + T - 1) / T, T>>>(hf, degf, bf, agg, NGLOB, 64);
    k_edge_agg_final<<<EGLOB / 8, 256>>>(eidx);
    k_logsoftmax<<<(NGLOB * 32 + T - 1) / T, T>>>(out);

    // --- second output: global_emb copy ---
    k_copy4<<<(NGLOB * 384 / 4 + T - 1) / T, T>>>((const float4*)gemb,
                                                  (float4*)(out + (size_t)NGLOB * NCLS),
                                                  NGLOB * 384 / 4);
}

// round 2
// speedup vs baseline: 1.9900x; 1.9900x over previous
#include <cuda_runtime.h>
#include <math.h>

#define S      64
#define NSUB   1024
#define ESUB   16384
#define NGLOB  65536
#define EGLOB  1048576
#define F      128
#define KPOOL  512
#define NCLS   64

// ---------------- scratch (device globals) ----------------
__device__ float g_h    [S*NSUB*F];
__device__ float g_x1   [S*NSUB*F];
__device__ float g_x2   [S*NSUB*F];
__device__ float g_hp   [S*NSUB];
__device__ float g_score[S*NSUB];
__device__ int   g_sel  [S*KPOOL];
__device__ int   g_pos  [S*NSUB];
__device__ float g_xpool[S*KPOOL*F];
__device__ float g_hpool[S*KPOOL*F];
__device__ float g_xsub [S*KPOOL*F];
__device__ float g_subemb[S*256];
__device__ float g_v    [S*256];
__device__ float g_att  [S*256];
__device__ float g_hf   [NGLOB*64];

__device__ float g_dinv [S*NSUB];
__device__ float g_dinv2[S*KPOOL];
__device__ float g_dinvf[NGLOB];

// CSR: subgraph edges (by dst, per subgraph slab)
__device__ int g_cntS [S*NSUB];
__device__ int g_stS  [S*NSUB];
__device__ int g_curS [S*NSUB];
__device__ int g_adjS [S*ESUB];
// CSR: global edges (by dst)
__device__ int g_cntG [NGLOB];
__device__ int g_stG  [NGLOB];
__device__ int g_curG [NGLOB];
__device__ int g_adjG [EGLOB];
// CSR: scatter rows (by sub_orig_idx)
__device__ int g_cntX [NGLOB];
__device__ int g_stX  [NGLOB];
__device__ int g_curX [NGLOB];
__device__ int g_adjX [S*NSUB];
__device__ int g_bsumG[64];
__device__ int g_bsumX[64];

// ---------------- utility ----------------
__global__ void k_zero(int* p, int n) {
    int i = blockIdx.x * blockDim.x + threadIdx.x;
    if (i < n) p[i] = 0;
}

// ---------------- SGEMM (unchanged from R1) ----------------
template<int BN, int TN>
__global__ void sgemm(const float* __restrict__ A, const float* __restrict__ B,
                      float* __restrict__ C, int M, int Kd, int Nc) {
    __shared__ float As[8][132];
    __shared__ float Bs[8][BN];
    int tid = threadIdx.x;
    int tx = tid & 15, ty = tid >> 4;
    int bx = blockIdx.x, by = blockIdx.y;
    const float* Ab = A + (size_t)by * 128 * Kd;
    const float* Bb = B + bx * BN;
    float acc[8][TN];
    #pragma unroll
    for (int i = 0; i < 8; i++)
        #pragma unroll
        for (int j = 0; j < TN; j++) acc[i][j] = 0.f;

    int arow = tid >> 1, acol = (tid & 1) * 4;
    for (int k0 = 0; k0 < Kd; k0 += 8) {
        float4 av = *(const float4*)(Ab + (size_t)arow * Kd + k0 + acol);
        As[acol + 0][arow] = av.x; As[acol + 1][arow] = av.y;
        As[acol + 2][arow] = av.z; As[acol + 3][arow] = av.w;
        if (BN == 128) {
            int brow = tid >> 5, bcol = (tid & 31) * 4;
            *(float4*)&Bs[brow][bcol] = *(const float4*)(Bb + (size_t)(k0 + brow) * Nc + bcol);
        } else {
            if (tid < 128) {
                int brow = tid >> 4, bcol = (tid & 15) * 4;
                *(float4*)&Bs[brow][bcol] = *(const float4*)(Bb + (size_t)(k0 + brow) * Nc + bcol);
            }
        }
        __syncthreads();
        #pragma unroll
        for (int k = 0; k < 8; k++) {
            float a[8], b[TN];
            #pragma unroll
            for (int i = 0; i < 8; i++)  a[i] = As[k][ty * 8 + i];
            #pragma unroll
            for (int j = 0; j < TN; j++) b[j] = Bs[k][tx * TN + j];
            #pragma unroll
            for (int i = 0; i < 8; i++)
                #pragma unroll
                for (int j = 0; j < TN; j++)
                    acc[i][j] += a[i] * b[j];
        }
        __syncthreads();
    }
    #pragma unroll
    for (int i = 0; i < 8; i++)
        #pragma unroll
        for (int j = 0; j < TN; j++)
            C[(size_t)(by * 128 + ty * 8 + i) * Nc + bx * BN + tx * TN + j] = acc[i][j];
}

// ---------------- CSR build: subgraph edges ----------------
__global__ void k_hist_sub(const int* __restrict__ sei) {
    int e = blockIdx.x * blockDim.x + threadIdx.x;
    if (e >= S * ESUB) return;
    int s = e / ESUB, j = e - s * ESUB;
    int dst = sei[s * 2 * ESUB + ESUB + j];
    atomicAdd(&g_cntS[s * NSUB + dst], 1);
}
__global__ void k_scan_sub() {   // block per subgraph, 1024 threads
    __shared__ int sh[1024];
    int s = blockIdx.x, t = threadIdx.x;
    int v = g_cntS[s * NSUB + t];
    sh[t] = v; __syncthreads();
    for (int o = 1; o < 1024; o <<= 1) {
        int x = (t >= o) ? sh[t - o] : 0;
        __syncthreads();
        sh[t] += x;
        __syncthreads();
    }
    int st = s * ESUB + sh[t] - v;
    g_stS[s * NSUB + t] = st;
    g_curS[s * NSUB + t] = st;
    g_dinv[s * NSUB + t] = rsqrtf((float)v + 1.f);
}
__global__ void k_adj_sub(const int* __restrict__ sei) {
    int e = blockIdx.x * blockDim.x + threadIdx.x;
    if (e >= S * ESUB) return;
    int s = e / ESUB, j = e - s * ESUB;
    int src = sei[s * 2 * ESUB + j];
    int dst = sei[s * 2 * ESUB + ESUB + j];
    g_adjS[atomicAdd(&g_curS[s * NSUB + dst], 1)] = src;
}

// ---------------- generic 65536-entry scan (64 blocks x 1024) ----------------
__global__ void k_hist32(const int* __restrict__ key, int* cnt, int n) {
    int i = blockIdx.x * blockDim.x + threadIdx.x;
    if (i < n) atomicAdd(&cnt[key[i]], 1);
}
__global__ void k_scan_block(const int* __restrict__ cnt, int* start, int* bsum) {
    __shared__ int sh[1024];
    int b = blockIdx.x, t = threadIdx.x, i = b * 1024 + t;
    int v = cnt[i];
    sh[t] = v; __syncthreads();
    for (int o = 1; o < 1024; o <<= 1) {
        int x = (t >= o) ? sh[t - o] : 0;
        __syncthreads();
        sh[t] += x;
        __syncthreads();
    }
    start[i] = sh[t] - v;
    if (t == 1023) bsum[b] = sh[t];
}
__global__ void k_scan_top(int* bsum, int n) {
    int acc = 0;
    for (int i = 0; i < n; i++) { int v = bsum[i]; bsum[i] = acc; acc += v; }
}
__global__ void k_scan_add(int* start, int* cur, const int* __restrict__ cnt,
                           const int* __restrict__ bsum, float* dinv) {
    int i = blockIdx.x * blockDim.x + threadIdx.x;
    if (i >= NGLOB) return;
    int v = start[i] + bsum[i >> 10];
    start[i] = v; cur[i] = v;
    if (dinv) dinv[i] = rsqrtf((float)cnt[i] + 1.f);
}
__global__ void k_adj_glob(const int* __restrict__ eidx) {
    int e = blockIdx.x * blockDim.x + threadIdx.x;
    if (e >= EGLOB) return;
    g_adjG[atomicAdd(&g_curG[eidx[EGLOB + e]], 1)] = eidx[e];
}
__global__ void k_adj_x(const int* __restrict__ sorig) {
    int i = blockIdx.x * blockDim.x + threadIdx.x;
    if (i >= S * NSUB) return;
    g_adjX[atomicAdd(&g_curX[sorig[i]], 1)] = i;
}

// ---------------- fused GCN layer (subgraph, F=128): warp per node ----------------
template<bool RELU>
__global__ void k_gcn_sub(const float* __restrict__ h, const float* __restrict__ bias,
                          float* __restrict__ outp) {
    int w = (blockIdx.x * blockDim.x + threadIdx.x) >> 5;
    int lane = threadIdx.x & 31;
    if (w >= S * NSUB) return;
    int s = w >> 10;
    int st = g_stS[w], cn = g_cntS[w];
    float4 acc = {0.f, 0.f, 0.f, 0.f};
    for (int base = 0; base < cn; base += 32) {
        int id = (base + lane < cn) ? g_adjS[st + base + lane] : 0;
        int m = min(32, cn - base);
        for (int k = 0; k < m; k++) {
            int src = s * NSUB + __shfl_sync(0xffffffffu, id, k);
            float c = __ldg(&g_dinv[src]);
            float4 v = __ldg((const float4*)(h + (size_t)src * F) + lane);
            acc.x += v.x * c; acc.y += v.y * c; acc.z += v.z * c; acc.w += v.w * c;
        }
    }
    float d = g_dinv[w];
    float4 hv = __ldg((const float4*)(h + (size_t)w * F) + lane);
    float4 bv = __ldg((const float4*)bias + lane);
    float4 r;
    r.x = acc.x * d + hv.x * d * d + bv.x;
    r.y = acc.y * d + hv.y * d * d + bv.y;
    r.z = acc.z * d + hv.z * d * d + bv.z;
    r.w = acc.w * d + hv.w * d * d + bv.w;
    if (RELU) {
        r.x = fmaxf(r.x, 0.f); r.y = fmaxf(r.y, 0.f);
        r.z = fmaxf(r.z, 0.f); r.w = fmaxf(r.w, 0.f);
    }
    ((float4*)(outp + (size_t)w * F))[lane] = r;
}

// ---------------- scorer GCN (1-dim) ----------------
__global__ void k_score_csr(const float* __restrict__ hp, const float* __restrict__ bp,
                            float* __restrict__ score) {
    int n = blockIdx.x * blockDim.x + threadIdx.x;
    if (n >= S * NSUB) return;
    int s = n >> 10;
    int st = g_stS[n], cn = g_cntS[n];
    float acc = 0.f;
    for (int k = 0; k < cn; k++) {
        int src = s * NSUB + g_adjS[st + k];
        acc += hp[src] * g_dinv[src];
    }
    float d = g_dinv[n];
    score[n] = acc * d + hp[n] * d * d + bp[0];
}

// ---------------- pooled graph degree ----------------
__global__ void k_deg_pool_csr() {
    int n = blockIdx.x * blockDim.x + threadIdx.x;
    if (n >= S * NSUB) return;
    int pd = g_pos[n];
    if (pd < 0) return;
    int s = n >> 10;
    int st = g_stS[n], cn = g_cntS[n], c = 0;
    for (int k = 0; k < cn; k++)
        if (g_pos[s * NSUB + g_adjS[st + k]] >= 0) c++;
    g_dinv2[s * KPOOL + pd] = rsqrtf((float)c + 1.f);
}

// ---------------- pooled GCN layer: warp per original node ----------------
__global__ void k_gcn_pool(const float* __restrict__ hpool, const float* __restrict__ bsc,
                           float* __restrict__ xsub) {
    int w = (blockIdx.x * blockDim.x + threadIdx.x) >> 5;
    int lane = threadIdx.x & 31;
    if (w >= S * NSUB) return;
    int pd = g_pos[w];
    if (pd < 0) return;
    int s = w >> 10;
    int st = g_stS[w], cn = g_cntS[w];
    float4 acc = {0.f, 0.f, 0.f, 0.f};
    for (int base = 0; base < cn; base += 32) {
        int id = (base + lane < cn) ? g_adjS[st + base + lane] : 0;
        int m = min(32, cn - base);
        for (int k = 0; k < m; k++) {
            int srcl = __shfl_sync(0xffffffffu, id, k);
            int ps = g_pos[s * NSUB + srcl];
            if (ps < 0) continue;
            int row = s * KPOOL + ps;
            float c = __ldg(&g_dinv2[row]);
            float4 v = __ldg((const float4*)(hpool + (size_t)row * F) + lane);
            acc.x += v.x * c; acc.y += v.y * c; acc.z += v.z * c; acc.w += v.w * c;
        }
    }
    int prow = s * KPOOL + pd;
    float d = g_dinv2[prow];
    float4 hv = __ldg((const float4*)(hpool + (size_t)prow * F) + lane);
    float4 bv = __ldg((const float4*)bsc + lane);
    float4 r;
    r.x = fmaxf(acc.x * d + hv.x * d * d + bv.x, 0.f);
    r.y = fmaxf(acc.y * d + hv.y * d * d + bv.y, 0.f);
    r.z = fmaxf(acc.z * d + hv.z * d * d + bv.z, 0.f);
    r.w = fmaxf(acc.w * d + hv.w * d * d + bv.w, 0.f);
    ((float4*)(xsub + (size_t)prow * F))[lane] = r;
}

// ---------------- scorer projection ----------------
__global__ void k_rowdot(const float* __restrict__ X, const float* __restrict__ w,
                         float* __restrict__ out, int rows) {
    int gw = (blockIdx.x * blockDim.x + threadIdx.x) >> 5;
    int lane = threadIdx.x & 31;
    if (gw >= rows) return;
    float4 x = ((const float4*)(X + (size_t)gw * F))[lane];
    float4 ww = ((const float4*)w)[lane];
    float acc = x.x * ww.x + x.y * ww.y + x.z * ww.z + x.w * ww.w;
    #pragma unroll
    for (int o = 16; o; o >>= 1) acc += __shfl_xor_sync(0xffffffffu, acc, o);
    if (lane == 0) out[gw] = acc;
}

// ---------------- top-512 of 1024 per subgraph ----------------
__global__ void k_topk() {
    __shared__ float vals[1024];
    __shared__ int   idxs[1024];
    int s = blockIdx.x, t = threadIdx.x;  // 512 threads
    vals[t]       = g_score[s * NSUB + t];       idxs[t]       = t;
    vals[t + 512] = g_score[s * NSUB + t + 512]; idxs[t + 512] = t + 512;
    g_pos[s * NSUB + t] = -1;
    g_pos[s * NSUB + t + 512] = -1;
    __syncthreads();
    for (int k2 = 2; k2 <= 1024; k2 <<= 1) {
        for (int j = k2 >> 1; j > 0; j >>= 1) {
            int i = ((t & ~(j - 1)) << 1) | (t & (j - 1));
            int ixj = i | j;
            bool ascend = ((i & k2) != 0);
            float vi = vals[i], vj = vals[ixj];
            bool sw = ascend ? (vi > vj) : (vi < vj);
            if (sw) {
                vals[i] = vj; vals[ixj] = vi;
                int tmp = idxs[i]; idxs[i] = idxs[ixj]; idxs[ixj] = tmp;
            }
            __syncthreads();
        }
    }
    int selidx = idxs[t];
    g_sel[s * KPOOL + t] = selidx;
    g_pos[s * NSUB + selidx] = t;
}

__global__ void k_xpool() {
    int i = blockIdx.x * blockDim.x + threadIdx.x;
    if (i >= S * KPOOL * F) return;
    int c = i & (F - 1);
    int rj = i >> 7;
    int s = rj >> 9;
    int sel = g_sel[rj];
    float gate = tanhf(g_score[s * NSUB + sel]);
    g_xpool[i] = g_x1[(size_t)(s * NSUB + sel) * F + c] * gate;
}

// ---------------- subgraph embedding: max+mean (512 thr/block) ----------------
__global__ void k_emb() {
    __shared__ float smx1[512], ssm1[512], smx2[512], ssm2[512];
    int s = blockIdx.x, t = threadIdx.x;
    int c = t & 127, part = t >> 7;   // 4 partitions of KPOOL rows
    const float* xp = g_xpool + (size_t)s * KPOOL * F + c;
    const float* xs = g_xsub  + (size_t)s * KPOOL * F + c;
    float mx1 = -INFINITY, sm1 = 0.f, mx2 = -INFINITY, sm2 = 0.f;
    for (int j = part; j < KPOOL; j += 4) {
        float v1 = xp[(size_t)j * F]; mx1 = fmaxf(mx1, v1); sm1 += v1;
        float v2 = xs[(size_t)j * F]; mx2 = fmaxf(mx2, v2); sm2 += v2;
    }
    smx1[t] = mx1; ssm1[t] = sm1; smx2[t] = mx2; ssm2[t] = sm2;
    __syncthreads();
    if (part == 0) {
        #pragma unroll
        for (int p = 1; p < 4; p++) {
            mx1 = fmaxf(mx1, smx1[p * 128 + c]); sm1 += ssm1[p * 128 + c];
            mx2 = fmaxf(mx2, smx2[p * 128 + c]); sm2 += ssm2[p * 128 + c];
        }
        g_subemb[s * 256 + c]       = mx1 + mx2;
        g_subemb[s * 256 + 128 + c] = (sm1 + sm2) * (1.f / KPOOL);
    }
}

// ---------------- small gemm (collapsed attention) ----------------
__global__ void k_small_gemm(const float* __restrict__ X, const float* __restrict__ W,
                             const float* __restrict__ b, float* __restrict__ out,
                             int ldw, int coloff, int Kd, int Ncols) {
    __shared__ float xs[256];
    int s = blockIdx.x;
    for (int i = threadIdx.x; i < Kd; i += blockDim.x) xs[i] = X[s * Kd + i];
    __syncthreads();
    int j = threadIdx.x;
    float acc = b[coloff + j];
    for (int k = 0; k < Kd; k++) acc += xs[k] * W[k * ldw + coloff + j];
    out[s * Ncols + j] = acc;
}

// ---------------- gather combined rows -> global embedding (in out buffer) ----------------
__global__ void k_gather_emb(float* __restrict__ gemb) {
    int n = blockIdx.x;       // NGLOB
    int c = threadIdx.x;      // 384
    int st = g_stX[n], cn = g_cntX[n];
    float acc = 0.f;
    for (int k = 0; k < cn; k++) {
        int row = g_adjX[st + k];
        int s = row >> 10;
        acc += (c < F) ? g_x2[(size_t)row * F + c] : g_att[s * 256 + (c - F)];
    }
    gemb[(size_t)n * 384 + c] = acc;
}

// ---------------- fused final GCN agg + log_softmax: warp per global node ----------------
__global__ void k_final(const float* __restrict__ hf, const float* __restrict__ bf,
                        float* __restrict__ out) {
    int w = (blockIdx.x * blockDim.x + threadIdx.x) >> 5;
    int lane = threadIdx.x & 31;
    if (w >= NGLOB) return;
    int st = g_stG[w], cn = g_cntG[w];
    float a = 0.f, b = 0.f;
    for (int base = 0; base < cn; base += 32) {
        int id = (base + lane < cn) ? g_adjG[st + base + lane] : 0;
        int m = min(32, cn - base);
        for (int k = 0; k < m; k++) {
            int src = __shfl_sync(0xffffffffu, id, k);
            float c = __ldg(&g_dinvf[src]);
            a += __ldg(&hf[(size_t)src * 64 + lane])      * c;
            b += __ldg(&hf[(size_t)src * 64 + 32 + lane]) * c;
        }
    }
    float d = g_dinvf[w];
    a = a * d + hf[(size_t)w * 64 + lane]      * d * d + bf[lane];
    b = b * d + hf[(size_t)w * 64 + 32 + lane] * d * d + bf[32 + lane];
    float m = fmaxf(a, b);
    #pragma unroll
    for (int o = 16; o; o >>= 1) m = fmaxf(m, __shfl_xor_sync(0xffffffffu, m, o));
    float ssum = expf(a - m) + expf(b - m);
    #pragma unroll
    for (int o = 16; o; o >>= 1) ssum += __shfl_xor_sync(0xffffffffu, ssum, o);
    float ls = m + logf(ssum);
    out[(size_t)w * 64 + lane]      = a - ls;
    out[(size_t)w * 64 + 32 + lane] = b - ls;
}

// ========================= host orchestration =========================
extern "C" void kernel_launch(void* const* d_in, const int* in_sizes, int n_in,
                              void* d_out, int out_size) {
    const float* sub_x = (const float*)d_in[0];
    const int*   sei   = (const int*)d_in[1];
    const int*   sorig = (const int*)d_in[2];
    const int*   eidx  = (const int*)d_in[3];
    const float* W1  = (const float*)d_in[4];
    const float* b1  = (const float*)d_in[5];
    const float* W2  = (const float*)d_in[6];
    const float* b2  = (const float*)d_in[7];
    const float* Wp  = (const float*)d_in[8];
    const float* bp  = (const float*)d_in[9];
    const float* Wsc = (const float*)d_in[10];
    const float* bsc = (const float*)d_in[11];
    const float* Wqkv= (const float*)d_in[12];
    const float* bqkv= (const float*)d_in[13];
    const float* Wo  = (const float*)d_in[14];
    const float* bo  = (const float*)d_in[15];
    const float* Wf  = (const float*)d_in[16];
    const float* bf  = (const float*)d_in[17];
    float* out = (float*)d_out;

    float *h, *x1, *x2, *hp, *score, *xpool, *hpool, *xsub, *subemb, *v, *att, *hf;
    float *dinvf;
    int *cntS, *cntG, *cntX, *stG, *stX, *curG, *curX, *bsumG, *bsumX;
    cudaGetSymbolAddress((void**)&h, g_h);
    cudaGetSymbolAddress((void**)&x1, g_x1);
    cudaGetSymbolAddress((void**)&x2, g_x2);
    cudaGetSymbolAddress((void**)&hp, g_hp);
    cudaGetSymbolAddress((void**)&score, g_score);
    cudaGetSymbolAddress((void**)&xpool, g_xpool);
    cudaGetSymbolAddress((void**)&hpool, g_hpool);
    cudaGetSymbolAddress((void**)&xsub, g_xsub);
    cudaGetSymbolAddress((void**)&subemb, g_subemb);
    cudaGetSymbolAddress((void**)&v, g_v);
    cudaGetSymbolAddress((void**)&att, g_att);
    cudaGetSymbolAddress((void**)&hf, g_hf);
    cudaGetSymbolAddress((void**)&dinvf, g_dinvf);
    cudaGetSymbolAddress((void**)&cntS, g_cntS);
    cudaGetSymbolAddress((void**)&cntG, g_cntG);
    cudaGetSymbolAddress((void**)&cntX, g_cntX);
    cudaGetSymbolAddress((void**)&stG, g_stG);
    cudaGetSymbolAddress((void**)&stX, g_stX);
    cudaGetSymbolAddress((void**)&curG, g_curG);
    cudaGetSymbolAddress((void**)&curX, g_curX);
    cudaGetSymbolAddress((void**)&bsumG, g_bsumG);
    cudaGetSymbolAddress((void**)&bsumX, g_bsumX);

    float* gemb = out + (size_t)NGLOB * NCLS;   // global_emb lives in the output buffer

    const int T = 256;
    const int ROWS = S * NSUB;          // 65536
    const int EDGES = S * ESUB;         // 1048576

    // --- CSR builds ---
    k_zero<<<ROWS / T, T>>>(cntS, ROWS);
    k_zero<<<NGLOB / T, T>>>(cntG, NGLOB);
    k_zero<<<NGLOB / T, T>>>(cntX, NGLOB);

    k_hist_sub<<<EDGES / T, T>>>(sei);
    k_scan_sub<<<S, 1024>>>();                  // also computes g_dinv
    k_adj_sub<<<EDGES / T, T>>>(sei);

    k_hist32<<<EGLOB / T, T>>>(eidx + EGLOB, cntG, EGLOB);
    k_scan_block<<<64, 1024>>>(cntG, stG, bsumG);
    k_scan_top<<<1, 1>>>(bsumG, 64);
    k_scan_add<<<NGLOB / T, T>>>(stG, curG, cntG, bsumG, dinvf);
    k_adj_glob<<<EGLOB / T, T>>>(eidx);

    k_hist32<<<ROWS / T, T>>>(sorig, cntX, ROWS);
    k_scan_block<<<64, 1024>>>(cntX, stX, bsumX);
    k_scan_top<<<1, 1>>>(bsumX, 64);
    k_scan_add<<<NGLOB / T, T>>>(stX, curX, cntX, bsumX, nullptr);
    k_adj_x<<<ROWS / T, T>>>(sorig);

    // --- GCN1 / GCN2 (fused init+agg+relu) ---
    sgemm<128, 8><<<dim3(1, ROWS / 128), 256>>>(sub_x, W1, h, ROWS, F, F);
    k_gcn_sub<true><<<ROWS * 32 / T, T>>>(h, b1, x1);
    sgemm<128, 8><<<dim3(1, ROWS / 128), 256>>>(x1, W2, h, ROWS, F, F);
    k_gcn_sub<true><<<ROWS * 32 / T, T>>>(h, b2, x2);

    // --- scorer + top-k pooling ---
    k_rowdot<<<ROWS * 32 / T, T>>>(x1, Wp, hp, ROWS);
    k_score_csr<<<ROWS / T, T>>>(hp, bp, score);
    k_topk<<<S, 512>>>();
    k_xpool<<<S * KPOOL * F / T, T>>>();

    // --- pooled GCN ---
    k_deg_pool_csr<<<ROWS / T, T>>>();
    sgemm<128, 8><<<dim3(1, (S * KPOOL) / 128), 256>>>(xpool, Wsc, hpool, S * KPOOL, F, F);
    k_gcn_pool<<<ROWS * 32 / T, T>>>(hpool, bsc, xsub);

    // --- subgraph embeddings + collapsed attention ---
    k_emb<<<S, 512>>>();
    k_small_gemm<<<S, 256>>>(subemb, Wqkv, bqkv, v, 768, 512, 256, 256);
    k_small_gemm<<<S, 256>>>(v, Wo, bo, att, 256, 0, 256, 256);

    // --- gather into global embedding (written straight into out) ---
    k_gather_emb<<<NGLOB, 384>>>(gemb);

    // --- final GCN + log_softmax (fused) ---
    sgemm<64, 4><<<dim3(1, NGLOB / 128), 256>>>(gemb, Wf, hf, NGLOB, 384, 64);
    k_final<<<NGLOB * 32 / T, T>>>(hf, bf, out);
}

// round 3
// speedup vs baseline: 2.2276x; 1.1194x over previous
#include <cuda_runtime.h>
#include <math.h>

#define S      64
#define NSUB   1024
#define ESUB   16384
#define NGLOB  65536
#define EGLOB  1048576
#define F      128
#define KPOOL  512
#define NCLS   64

// ---------------- scratch (device globals) ----------------
__device__ float g_h    [S*NSUB*F];
__device__ float g_x1   [S*NSUB*F];
__device__ float g_x2   [S*NSUB*F];
__device__ float g_hp   [S*NSUB];
__device__ float g_score[S*NSUB];
__device__ int   g_sel  [S*KPOOL];
__device__ int   g_pos  [S*NSUB];
__device__ float g_xpool[S*KPOOL*F];
__device__ float g_hpool[S*KPOOL*F];
__device__ float g_xsub [S*KPOOL*F];
__device__ float g_subemb[S*256];
__device__ float g_v    [S*256];
__device__ float g_att  [S*256];
__device__ float g_hf   [NGLOB*64];

__device__ float g_dinv [S*NSUB];
__device__ float g_dinv2[S*KPOOL];
__device__ float g_dinvf[NGLOB];

// CSR: subgraph edges (by dst, per subgraph slab)
__device__ int g_cntS [S*NSUB];
__device__ int g_stS  [S*NSUB];
__device__ int g_adjS [S*ESUB];
// CSR: global edges (by dst)
__device__ int g_cntG [NGLOB];
__device__ int g_stG  [NGLOB];
__device__ int g_curG [NGLOB];
__device__ int g_adjG [EGLOB];
// CSR: scatter rows (by sub_orig_idx)
__device__ int g_cntX [NGLOB];
__device__ int g_stX  [NGLOB];
__device__ int g_curX [NGLOB];
__device__ int g_adjX [S*NSUB];
__device__ int g_bsumG[64];
__device__ int g_bsumX[64];

// ---------------- utility ----------------
__global__ void k_zero(int* p, int n) {
    int i = blockIdx.x * blockDim.x + threadIdx.x;
    if (i < n) p[i] = 0;
}

// ============ SGEMM v2: packed f32x2 FMA, double-buffered shared ============
// C[M,Nc] = A[M,K] @ B[K,Nc].  BM=128, BK=8, BN in {128,64}.
// Thread tile 8x8 laid out as 8 rows x 4 col-pairs (f32x2 accumulators).
template<int BN>
__global__ void __launch_bounds__(BN * 2, 2)
sgemm2(const float* __restrict__ A, const float* __restrict__ B,
       float* __restrict__ C, int M, int Kd, int Nc) {
    constexpr int TX = BN / 8;            // 16 or 8
    constexpr int NT = TX * 16;           // 256 or 128
    constexpr int AL = 1024 / NT / 4;     // float4 A-loads per thread (1 or 2)
    __shared__ float As[2][8][128];       // transposed: [k][row]
    __shared__ float Bs[2][8][BN];

    int tid = threadIdx.x;
    int tx = tid % TX, ty = tid / TX;
    const float* Ab = A + (size_t)blockIdx.y * 128 * Kd;
    const float* Bb = B + blockIdx.x * BN;

    unsigned long long acc[8][4];
    #pragma unroll
    for (int i = 0; i < 8; i++)
        #pragma unroll
        for (int j = 0; j < 4; j++) acc[i][j] = 0ull;

    float4 pa[AL], pb;
    int brow = tid / (BN / 4), bcol = (tid % (BN / 4)) * 4;

    // prefetch chunk 0
    #pragma unroll
    for (int l = 0; l < AL; l++) {
        int idx = tid + l * NT, row = idx >> 1, kc = (idx & 1) * 4;
        pa[l] = *(const float4*)(Ab + (size_t)row * Kd + kc);
    }
    pb = *(const float4*)(Bb + (size_t)brow * Nc + bcol);
    #pragma unroll
    for (int l = 0; l < AL; l++) {
        int idx = tid + l * NT, row = idx >> 1, kc = (idx & 1) * 4;
        As[0][kc + 0][row] = pa[l].x; As[0][kc + 1][row] = pa[l].y;
        As[0][kc + 2][row] = pa[l].z; As[0][kc + 3][row] = pa[l].w;
    }
    *(float4*)&Bs[0][brow][bcol] = pb;
    __syncthreads();

    int nch = Kd >> 3;
    for (int c = 0; c < nch; c++) {
        int cur = c & 1;
        if (c + 1 < nch) {
            int k0 = (c + 1) * 8;
            #pragma unroll
            for (int l = 0; l < AL; l++) {
                int idx = tid + l * NT, row = idx >> 1, kc = (idx & 1) * 4;
                pa[l] = *(const float4*)(Ab + (size_t)row * Kd + k0 + kc);
            }
            pb = *(const float4*)(Bb + (size_t)(k0 + brow) * Nc + bcol);
        }
        #pragma unroll
        for (int k = 0; k < 8; k++) {
            uint4 a03 = *(const uint4*)&As[cur][k][ty * 8];
            uint4 a47 = *(const uint4*)&As[cur][k][ty * 8 + 4];
            ulonglong2 b01 = *(const ulonglong2*)&Bs[cur][k][tx * 8];
            ulonglong2 b23 = *(const ulonglong2*)&Bs[cur][k][tx * 8 + 4];
            unsigned long long bb0 = b01.x, bb1 = b01.y, bb2 = b23.x, bb3 = b23.y;
            unsigned int av[8] = {a03.x, a03.y, a03.z, a03.w,
                                  a47.x, a47.y, a47.z, a47.w};
            #pragma unroll
            for (int i = 0; i < 8; i++) {
                unsigned long long aa;
                asm("mov.b64 %0, {%1, %1};" : "=l"(aa) : "r"(av[i]));
                asm("fma.rn.f32x2 %0, %1, %2, %0;" : "+l"(acc[i][0]) : "l"(aa), "l"(bb0));
                asm("fma.rn.f32x2 %0, %1, %2, %0;" : "+l"(acc[i][1]) : "l"(aa), "l"(bb1));
                asm("fma.rn.f32x2 %0, %1, %2, %0;" : "+l"(acc[i][2]) : "l"(aa), "l"(bb2));
                asm("fma.rn.f32x2 %0, %1, %2, %0;" : "+l"(acc[i][3]) : "l"(aa), "l"(bb3));
            }
        }
        if (c + 1 < nch) {
            int nb = cur ^ 1;
            #pragma unroll
            for (int l = 0; l < AL; l++) {
                int idx = tid + l * NT, row = idx >> 1, kc = (idx & 1) * 4;
                As[nb][kc + 0][row] = pa[l].x; As[nb][kc + 1][row] = pa[l].y;
                As[nb][kc + 2][row] = pa[l].z; As[nb][kc + 3][row] = pa[l].w;
            }
            *(float4*)&Bs[nb][brow][bcol] = pb;
            __syncthreads();
        }
    }

    int row0 = blockIdx.y * 128 + ty * 8;
    int col0 = blockIdx.x * BN + tx * 8;
    #pragma unroll
    for (int i = 0; i < 8; i++) {
        float2 f0 = *(float2*)&acc[i][0];
        float2 f1 = *(float2*)&acc[i][1];
        float2 f2 = *(float2*)&acc[i][2];
        float2 f3 = *(float2*)&acc[i][3];
        float4 o0 = make_float4(f0.x, f0.y, f1.x, f1.y);
        float4 o1 = make_float4(f2.x, f2.y, f3.x, f3.y);
        *(float4*)&C[(size_t)(row0 + i) * Nc + col0]     = o0;
        *(float4*)&C[(size_t)(row0 + i) * Nc + col0 + 4] = o1;
    }
}

// ---------------- fully fused subgraph CSR build (block per subgraph) ----------------
__global__ void k_csr_sub(const int* __restrict__ sei) {
    __shared__ int cnt[1024];
    __shared__ int cur[1024];
    int s = blockIdx.x, t = threadIdx.x;   // 1024 threads
    cnt[t] = 0;
    __syncthreads();
    const int* base = sei + s * 2 * ESUB;
    #pragma unroll
    for (int e = t; e < ESUB; e += 1024)
        atomicAdd(&cnt[base[ESUB + e]], 1);
    __syncthreads();
    int v = cnt[t];
    cur[t] = v; __syncthreads();
    #pragma unroll
    for (int o = 1; o < 1024; o <<= 1) {
        int x = (t >= o) ? cur[t - o] : 0;
        __syncthreads();
        cur[t] += x;
        __syncthreads();
    }
    int loc = cur[t] - v;                  // exclusive scan, local offset
    g_stS[s * NSUB + t]  = s * ESUB + loc;
    g_cntS[s * NSUB + t] = v;
    g_dinv[s * NSUB + t] = rsqrtf((float)v + 1.f);
    __syncthreads();
    cur[t] = loc;
    __syncthreads();
    #pragma unroll
    for (int e = t; e < ESUB; e += 1024) {
        int src = base[e], dst = base[ESUB + e];
        int p = atomicAdd(&cur[dst], 1);
        g_adjS[s * ESUB + p] = src;
    }
}

// ---------------- generic 65536-entry scan (64 blocks x 1024) ----------------
__global__ void k_hist32(const int* __restrict__ key, int* cnt, int n) {
    int i = blockIdx.x * blockDim.x + threadIdx.x;
    if (i < n) atomicAdd(&cnt[key[i]], 1);
}
__global__ void k_scan_block(const int* __restrict__ cnt, int* start, int* bsum) {
    __shared__ int sh[1024];
    int b = blockIdx.x, t = threadIdx.x, i = b * 1024 + t;
    int v = cnt[i];
    sh[t] = v; __syncthreads();
    for (int o = 1; o < 1024; o <<= 1) {
        int x = (t >= o) ? sh[t - o] : 0;
        __syncthreads();
        sh[t] += x;
        __syncthreads();
    }
    start[i] = sh[t] - v;
    if (t == 1023) bsum[b] = sh[t];
}
__global__ void k_scan_top(int* bsum, int n) {
    int acc = 0;
    for (int i = 0; i < n; i++) { int v = bsum[i]; bsum[i] = acc; acc += v; }
}
__global__ void k_scan_add(int* start, int* cur, const int* __restrict__ cnt,
                           const int* __restrict__ bsum, float* dinv) {
    int i = blockIdx.x * blockDim.x + threadIdx.x;
    if (i >= NGLOB) return;
    int v = start[i] + bsum[i >> 10];
    start[i] = v; cur[i] = v;
    if (dinv) dinv[i] = rsqrtf((float)cnt[i] + 1.f);
}
__global__ void k_adj_glob(const int* __restrict__ eidx) {
    int e = blockIdx.x * blockDim.x + threadIdx.x;
    if (e >= EGLOB) return;
    g_adjG[atomicAdd(&g_curG[eidx[EGLOB + e]], 1)] = eidx[e];
}
__global__ void k_adj_x(const int* __restrict__ sorig) {
    int i = blockIdx.x * blockDim.x + threadIdx.x;
    if (i >= S * NSUB) return;
    g_adjX[atomicAdd(&g_curX[sorig[i]], 1)] = i;
}

// ---------------- fused GCN layer (subgraph, F=128): warp per node ----------------
template<bool RELU>
__global__ void k_gcn_sub(const float* __restrict__ h, const float* __restrict__ bias,
                          float* __restrict__ outp) {
    int w = (blockIdx.x * blockDim.x + threadIdx.x) >> 5;
    int lane = threadIdx.x & 31;
    if (w >= S * NSUB) return;
    int s = w >> 10;
    int st = g_stS[w], cn = g_cntS[w];
    float4 acc = {0.f, 0.f, 0.f, 0.f};
    for (int base = 0; base < cn; base += 32) {
        int id = (base + lane < cn) ? g_adjS[st + base + lane] : 0;
        int m = min(32, cn - base);
        for (int k = 0; k < m; k++) {
            int src = s * NSUB + __shfl_sync(0xffffffffu, id, k);
            float c = __ldg(&g_dinv[src]);
            float4 v = __ldg((const float4*)(h + (size_t)src * F) + lane);
            acc.x += v.x * c; acc.y += v.y * c; acc.z += v.z * c; acc.w += v.w * c;
        }
    }
    float d = g_dinv[w];
    float4 hv = __ldg((const float4*)(h + (size_t)w * F) + lane);
    float4 bv = __ldg((const float4*)bias + lane);
    float4 r;
    r.x = acc.x * d + hv.x * d * d + bv.x;
    r.y = acc.y * d + hv.y * d * d + bv.y;
    r.z = acc.z * d + hv.z * d * d + bv.z;
    r.w = acc.w * d + hv.w * d * d + bv.w;
    if (RELU) {
        r.x = fmaxf(r.x, 0.f); r.y = fmaxf(r.y, 0.f);
        r.z = fmaxf(r.z, 0.f); r.w = fmaxf(r.w, 0.f);
    }
    ((float4*)(outp + (size_t)w * F))[lane] = r;
}

// ---------------- scorer GCN (1-dim) ----------------
__global__ void k_score_csr(const float* __restrict__ hp, const float* __restrict__ bp,
                            float* __restrict__ score) {
    int n = blockIdx.x * blockDim.x + threadIdx.x;
    if (n >= S * NSUB) return;
    int s = n >> 10;
    int st = g_stS[n], cn = g_cntS[n];
    float acc = 0.f;
    for (int k = 0; k < cn; k++) {
        int src = s * NSUB + g_adjS[st + k];
        acc += hp[src] * g_dinv[src];
    }
    float d = g_dinv[n];
    score[n] = acc * d + hp[n] * d * d + bp[0];
}

// ---------------- pooled graph degree ----------------
__global__ void k_deg_pool_csr() {
    int n = blockIdx.x * blockDim.x + threadIdx.x;
    if (n >= S * NSUB) return;
    int pd = g_pos[n];
    if (pd < 0) return;
    int s = n >> 10;
    int st = g_stS[n], cn = g_cntS[n], c = 0;
    for (int k = 0; k < cn; k++)
        if (g_pos[s * NSUB + g_adjS[st + k]] >= 0) c++;
    g_dinv2[s * KPOOL + pd] = rsqrtf((float)c + 1.f);
}

// ---------------- pooled GCN layer: warp per original node ----------------
__global__ void k_gcn_pool(const float* __restrict__ hpool, const float* __restrict__ bsc,
                           float* __restrict__ xsub) {
    int w = (blockIdx.x * blockDim.x + threadIdx.x) >> 5;
    int lane = threadIdx.x & 31;
    if (w >= S * NSUB) return;
    int pd = g_pos[w];
    if (pd < 0) return;
    int s = w >> 10;
    int st = g_stS[w], cn = g_cntS[w];
    float4 acc = {0.f, 0.f, 0.f, 0.f};
    for (int base = 0; base < cn; base += 32) {
        int id = (base + lane < cn) ? g_adjS[st + base + lane] : 0;
        int m = min(32, cn - base);
        for (int k = 0; k < m; k++) {
            int srcl = __shfl_sync(0xffffffffu, id, k);
            int ps = g_pos[s * NSUB + srcl];
            if (ps < 0) continue;
            int row = s * KPOOL + ps;
            float c = __ldg(&g_dinv2[row]);
            float4 v = __ldg((const float4*)(hpool + (size_t)row * F) + lane);
            acc.x += v.x * c; acc.y += v.y * c; acc.z += v.z * c; acc.w += v.w * c;
        }
    }
    int prow = s * KPOOL + pd;
    float d = g_dinv2[prow];
    float4 hv = __ldg((const float4*)(hpool + (size_t)prow * F) + lane);
    float4 bv = __ldg((const float4*)bsc + lane);
    float4 r;
    r.x = fmaxf(acc.x * d + hv.x * d * d + bv.x, 0.f);
    r.y = fmaxf(acc.y * d + hv.y * d * d + bv.y, 0.f);
    r.z = fmaxf(acc.z * d + hv.z * d * d + bv.z, 0.f);
    r.w = fmaxf(acc.w * d + hv.w * d * d + bv.w, 0.f);
    ((float4*)(xsub + (size_t)prow * F))[lane] = r;
}

// ---------------- scorer projection ----------------
__global__ void k_rowdot(const float* __restrict__ X, const float* __restrict__ w,
                         float* __restrict__ out, int rows) {
    int gw = (blockIdx.x * blockDim.x + threadIdx.x) >> 5;
    int lane = threadIdx.x & 31;
    if (gw >= rows) return;
    float4 x = ((const float4*)(X + (size_t)gw * F))[lane];
    float4 ww = ((const float4*)w)[lane];
    float acc = x.x * ww.x + x.y * ww.y + x.z * ww.z + x.w * ww.w;
    #pragma unroll
    for (int o = 16; o; o >>= 1) acc += __shfl_xor_sync(0xffffffffu, acc, o);
    if (lane == 0) out[gw] = acc;
}

// ---------------- top-512 of 1024 per subgraph ----------------
__global__ void k_topk() {
    __shared__ float vals[1024];
    __shared__ int   idxs[1024];
    int s = blockIdx.x, t = threadIdx.x;  // 512 threads
    vals[t]       = g_score[s * NSUB + t];       idxs[t]       = t;
    vals[t + 512] = g_score[s * NSUB + t + 512]; idxs[t + 512] = t + 512;
    g_pos[s * NSUB + t] = -1;
    g_pos[s * NSUB + t + 512] = -1;
    __syncthreads();
    for (int k2 = 2; k2 <= 1024; k2 <<= 1) {
        for (int j = k2 >> 1; j > 0; j >>= 1) {
            int i = ((t & ~(j - 1)) << 1) | (t & (j - 1));
            int ixj = i | j;
            bool ascend = ((i & k2) != 0);
            float vi = vals[i], vj = vals[ixj];
            bool sw = ascend ? (vi > vj) : (vi < vj);
            if (sw) {
                vals[i] = vj; vals[ixj] = vi;
                int tmp = idxs[i]; idxs[i] = idxs[ixj]; idxs[ixj] = tmp;
            }
            __syncthreads();
        }
    }
    int selidx = idxs[t];
    g_sel[s * KPOOL + t] = selidx;
    g_pos[s * NSUB + selidx] = t;
}

__global__ void k_xpool() {
    int i = blockIdx.x * blockDim.x + threadIdx.x;
    if (i >= S * KPOOL * F) return;
    int c = i & (F - 1);
    int rj = i >> 7;
    int s = rj >> 9;
    int sel = g_sel[rj];
    float gate = tanhf(g_score[s * NSUB + sel]);
    g_xpool[i] = g_x1[(size_t)(s * NSUB + sel) * F + c] * gate;
}

// ---------------- subgraph embedding: max+mean (512 thr/block) ----------------
__global__ void k_emb() {
    __shared__ float smx1[512], ssm1[512], smx2[512], ssm2[512];
    int s = blockIdx.x, t = threadIdx.x;
    int c = t & 127, part = t >> 7;
    const float* xp = g_xpool + (size_t)s * KPOOL * F + c;
    const float* xs = g_xsub  + (size_t)s * KPOOL * F + c;
    float mx1 = -INFINITY, sm1 = 0.f, mx2 = -INFINITY, sm2 = 0.f;
    for (int j = part; j < KPOOL; j += 4) {
        float v1 = xp[(size_t)j * F]; mx1 = fmaxf(mx1, v1); sm1 += v1;
        float v2 = xs[(size_t)j * F]; mx2 = fmaxf(mx2, v2); sm2 += v2;
    }
    smx1[t] = mx1; ssm1[t] = sm1; smx2[t] = mx2; ssm2[t] = sm2;
    __syncthreads();
    if (part == 0) {
        #pragma unroll
        for (int p = 1; p < 4; p++) {
            mx1 = fmaxf(mx1, smx1[p * 128 + c]); sm1 += ssm1[p * 128 + c];
            mx2 = fmaxf(mx2, smx2[p * 128 + c]); sm2 += ssm2[p * 128 + c];
        }
        g_subemb[s * 256 + c]       = mx1 + mx2;
        g_subemb[s * 256 + 128 + c] = (sm1 + sm2) * (1.f / KPOOL);
    }
}

// ---------------- small gemm (collapsed attention) ----------------
__global__ void k_small_gemm(const float* __restrict__ X, const float* __restrict__ W,
                             const float* __restrict__ b, float* __restrict__ out,
                             int ldw, int coloff, int Kd, int Ncols) {
    __shared__ float xs[256];
    int s = blockIdx.x;
    for (int i = threadIdx.x; i < Kd; i += blockDim.x) xs[i] = X[s * Kd + i];
    __syncthreads();
    int j = threadIdx.x;
    float acc = b[coloff + j];
    for (int k = 0; k < Kd; k++) acc += xs[k] * W[k * ldw + coloff + j];
    out[s * Ncols + j] = acc;
}

// ---------------- gather combined rows -> global embedding (in out buffer) ----------------
__global__ void k_gather_emb(float* __restrict__ gemb) {
    int n = blockIdx.x;
    int c = threadIdx.x;      // 384
    int st = g_stX[n], cn = g_cntX[n];
    float acc = 0.f;
    for (int k = 0; k < cn; k++) {
        int row = g_adjX[st + k];
        int s = row >> 10;
        acc += (c < F) ? g_x2[(size_t)row * F + c] : g_att[s * 256 + (c - F)];
    }
    gemb[(size_t)n * 384 + c] = acc;
}

// ---------------- fused final GCN agg + log_softmax: warp per global node ----------------
__global__ void k_final(const float* __restrict__ hf, const float* __restrict__ bf,
                        float* __restrict__ out) {
    int w = (blockIdx.x * blockDim.x + threadIdx.x) >> 5;
    int lane = threadIdx.x & 31;
    if (w >= NGLOB) return;
    int st = g_stG[w], cn = g_cntG[w];
    float a = 0.f, b = 0.f;
    for (int base = 0; base < cn; base += 32) {
        int id = (base + lane < cn) ? g_adjG[st + base + lane] : 0;
        int m = min(32, cn - base);
        for (int k = 0; k < m; k++) {
            int src = __shfl_sync(0xffffffffu, id, k);
            float c = __ldg(&g_dinvf[src]);
            a += __ldg(&hf[(size_t)src * 64 + lane])      * c;
            b += __ldg(&hf[(size_t)src * 64 + 32 + lane]) * c;
        }
    }
    float d = g_dinvf[w];
    a = a * d + hf[(size_t)w * 64 + lane]      * d * d + bf[lane];
    b = b * d + hf[(size_t)w * 64 + 32 + lane] * d * d + bf[32 + lane];
    float m = fmaxf(a, b);
    #pragma unroll
    for (int o = 16; o; o >>= 1) m = fmaxf(m, __shfl_xor_sync(0xffffffffu, m, o));
    float ssum = expf(a - m) + expf(b - m);
    #pragma unroll
    for (int o = 16; o; o >>= 1) ssum += __shfl_xor_sync(0xffffffffu, ssum, o);
    float ls = m + logf(ssum);
    out[(size_t)w * 64 + lane]      = a - ls;
    out[(size_t)w * 64 + 32 + lane] = b - ls;
}

// ========================= host orchestration =========================
extern "C" void kernel_launch(void* const* d_in, const int* in_sizes, int n_in,
                              void* d_out, int out_size) {
    const float* sub_x = (const float*)d_in[0];
    const int*   sei   = (const int*)d_in[1];
    const int*   sorig = (const int*)d_in[2];
    const int*   eidx  = (const int*)d_in[3];
    const float* W1  = (const float*)d_in[4];
    const float* b1  = (const float*)d_in[5];
    const float* W2  = (const float*)d_in[6];
    const float* b2  = (const float*)d_in[7];
    const float* Wp  = (const float*)d_in[8];
    const float* bp  = (const float*)d_in[9];
    const float* Wsc = (const float*)d_in[10];
    const float* bsc = (const float*)d_in[11];
    const float* Wqkv= (const float*)d_in[12];
    const float* bqkv= (const float*)d_in[13];
    const float* Wo  = (const float*)d_in[14];
    const float* bo  = (const float*)d_in[15];
    const float* Wf  = (const float*)d_in[16];
    const float* bf  = (const float*)d_in[17];
    float* out = (float*)d_out;

    float *h, *x1, *x2, *hp, *score, *xpool, *hpool, *xsub, *subemb, *v, *att, *hf;
    float *dinvf;
    int *cntG, *cntX, *stG, *stX, *curG, *curX, *bsumG, *bsumX;
    cudaGetSymbolAddress((void**)&h, g_h);
    cudaGetSymbolAddress((void**)&x1, g_x1);
    cudaGetSymbolAddress((void**)&x2, g_x2);
    cudaGetSymbolAddress((void**)&hp, g_hp);
    cudaGetSymbolAddress((void**)&score, g_score);
    cudaGetSymbolAddress((void**)&xpool, g_xpool);
    cudaGetSymbolAddress((void**)&hpool, g_hpool);
    cudaGetSymbolAddress((void**)&xsub, g_xsub);
    cudaGetSymbolAddress((void**)&subemb, g_subemb);
    cudaGetSymbolAddress((void**)&v, g_v);
    cudaGetSymbolAddress((void**)&att, g_att);
    cudaGetSymbolAddress((void**)&hf, g_hf);
    cudaGetSymbolAddress((void**)&dinvf, g_dinvf);
    cudaGetSymbolAddress((void**)&cntG, g_cntG);
    cudaGetSymbolAddress((void**)&cntX, g_cntX);
    cudaGetSymbolAddress((void**)&stG, g_stG);
    cudaGetSymbolAddress((void**)&stX, g_stX);
    cudaGetSymbolAddress((void**)&curG, g_curG);
    cudaGetSymbolAddress((void**)&curX, g_curX);
    cudaGetSymbolAddress((void**)&bsumG, g_bsumG);
    cudaGetSymbolAddress((void**)&bsumX, g_bsumX);

    float* gemb = out + (size_t)NGLOB * NCLS;   // global_emb lives in the output buffer

    const int T = 256;
    const int ROWS = S * NSUB;          // 65536
    const int EDGES = S * ESUB;         // 1048576

    // --- subgraph CSR (single fused kernel) ---
    k_csr_sub<<<S, 1024>>>(sei);

    // --- global / scatter CSRs ---
    k_zero<<<NGLOB / T, T>>>(cntG, NGLOB);
    k_zero<<<NGLOB / T, T>>>(cntX, NGLOB);

    k_hist32<<<EGLOB / T, T>>>(eidx + EGLOB, cntG, EGLOB);
    k_scan_block<<<64, 1024>>>(cntG, stG, bsumG);
    k_scan_top<<<1, 1>>>(bsumG, 64);
    k_scan_add<<<NGLOB / T, T>>>(stG, curG, cntG, bsumG, dinvf);
    k_adj_glob<<<EGLOB / T, T>>>(eidx);

    k_hist32<<<ROWS / T, T>>>(sorig, cntX, ROWS);
    k_scan_block<<<64, 1024>>>(cntX, stX, bsumX);
    k_scan_top<<<1, 1>>>(bsumX, 64);
    k_scan_add<<<NGLOB / T, T>>>(stX, curX, cntX, bsumX, nullptr);
    k_adj_x<<<ROWS / T, T>>>(sorig);

    // --- GCN1 / GCN2 (fused init+agg+relu) ---
    sgemm2<128><<<dim3(1, ROWS / 128), 256>>>(sub_x, W1, h, ROWS, F, F);
    k_gcn_sub<true><<<ROWS * 32 / T, T>>>(h, b1, x1);
    sgemm2<128><<<dim3(1, ROWS / 128), 256>>>(x1, W2, h, ROWS, F, F);
    k_gcn_sub<true><<<ROWS * 32 / T, T>>>(h, b2, x2);

    // --- scorer + top-k pooling ---
    k_rowdot<<<ROWS * 32 / T, T>>>(x1, Wp, hp, ROWS);
    k_score_csr<<<ROWS / T, T>>>(hp, bp, score);
    k_topk<<<S, 512>>>();
    k_xpool<<<S * KPOOL * F / T, T>>>();

    // --- pooled GCN ---
    k_deg_pool_csr<<<ROWS / T, T>>>();
    sgemm2<128><<<dim3(1, (S * KPOOL) / 128), 256>>>(xpool, Wsc, hpool, S * KPOOL, F, F);
    k_gcn_pool<<<ROWS * 32 / T, T>>>(hpool, bsc, xsub);

    // --- subgraph embeddings + collapsed attention ---
    k_emb<<<S, 512>>>();
    k_small_gemm<<<S, 256>>>(subemb, Wqkv, bqkv, v, 768, 512, 256, 256);
    k_small_gemm<<<S, 256>>>(v, Wo, bo, att, 256, 0, 256, 256);

    // --- gather into global embedding (written straight into out) ---
    k_gather_emb<<<NGLOB, 384>>>(gemb);

    // --- final GCN + log_softmax (fused) ---
    sgemm2<64><<<dim3(1, NGLOB / 128), 128>>>(gemb, Wf, hf, NGLOB, 384, 64);
    k_final<<<NGLOB * 32 / T, T>>>(hf, bf, out);
}

// round 4
// speedup vs baseline: 2.5141x; 1.1286x over previous
#include <cuda_runtime.h>
#include <math.h>

#define S      64
#define NSUB   1024
#define ESUB   16384
#define NGLOB  65536
#define EGLOB  1048576
#define F      128
#define KPOOL  512
#define NCLS   64

// ---------------- scratch (device globals) ----------------
__device__ float g_h    [S*NSUB*F];
__device__ float g_x1   [S*NSUB*F];
__device__ float g_x2   [S*NSUB*F];
__device__ float g_hp   [S*NSUB];
__device__ float g_score[S*NSUB];
__device__ int   g_sel  [S*KPOOL];
__device__ int   g_pos  [S*NSUB];
__device__ float g_xpool[S*KPOOL*F];
__device__ float g_hpool[S*KPOOL*F];
__device__ float g_xsub [S*KPOOL*F];
__device__ float g_subemb[S*256];
__device__ float g_v    [S*256];
__device__ float g_att  [S*256];
__device__ float g_hf   [NGLOB*64];

__device__ float g_dinv [S*NSUB];
__device__ float g_dinv2[S*KPOOL];
__device__ float g_dinvf[NGLOB];

// CSR: subgraph edges (by dst, per subgraph slab)
__device__ int g_cntS [S*NSUB];
__device__ int g_stS  [S*NSUB];
__device__ int g_adjS [S*ESUB];
// CSR: global edges (by dst)
__device__ int g_cntG [NGLOB];
__device__ int g_stG  [NGLOB];
__device__ int g_curG [NGLOB];
__device__ int g_adjG [EGLOB];
// CSR: scatter rows (by sub_orig_idx)
__device__ int g_cntX [NGLOB];
__device__ int g_stX  [NGLOB];
__device__ int g_curX [NGLOB];
__device__ int g_adjX [S*NSUB];
__device__ int g_bsumG[64];
__device__ int g_bsumX[64];

// ---------------- utility ----------------
__global__ void k_zero(int* p, int n) {
    int i = blockIdx.x * blockDim.x + threadIdx.x;
    if (i < n) p[i] = 0;
}

// ============ GEMM v3: tensor-core 3xTF32 (mma.sync.m16n8k8) ============
// C[M,Nc] = A[M,K] @ B[K,Nc], fp32 in/out, ~fp32 accuracy via tf32 hi/lo split.
// Block: 128 rows x 64 cols, 256 threads = 8 warps (4 row x 2 col),
// warp tile 32x32 (2 m16-tiles x 4 n8-tiles). K chunks of 32, double buffered.
#define ASTR 36
#define BSTR 72
#define A_BUF (128 * ASTR)
#define B_BUF (32 * BSTR)
#define TG_SMEM ((2 * A_BUF + 2 * B_BUF) * 4)

__device__ __forceinline__ void tf32_split(float a, unsigned& hi, unsigned& lo) {
    asm("cvt.rna.tf32.f32 %0, %1;" : "=r"(hi) : "f"(a));
    float r = a - __uint_as_float(hi);
    asm("cvt.rna.tf32.f32 %0, %1;" : "=r"(lo) : "f"(r));
}
__device__ __forceinline__ void mma8(float c[4], const unsigned a[4], const unsigned b[2]) {
    asm("mma.sync.aligned.m16n8k8.row.col.f32.tf32.tf32.f32 "
        "{%0,%1,%2,%3}, {%4,%5,%6,%7}, {%8,%9}, {%0,%1,%2,%3};"
        : "+f"(c[0]), "+f"(c[1]), "+f"(c[2]), "+f"(c[3])
        : "r"(a[0]), "r"(a[1]), "r"(a[2]), "r"(a[3]), "r"(b[0]), "r"(b[1]));
}

__global__ void __launch_bounds__(256, 2)
tgemm(const float* __restrict__ A, const float* __restrict__ B,
      float* __restrict__ C, int M, int Kd, int Nc) {
    extern __shared__ float sm[];
    float* As = sm;                    // [2][128][ASTR]  layout [m][k]
    float* Bs = sm + 2 * A_BUF;        // [2][32][BSTR]   layout [k][n]

    int tid = threadIdx.x;
    int wid = tid >> 5, lane = tid & 31;
    int g = lane >> 2, tig = lane & 3;
    int wr = wid & 3, wc = wid >> 2;
    int mw = wr * 32, nw = wc * 32;
    const float* Ab = A + (size_t)blockIdx.y * 128 * Kd;
    const float* Bb = B + blockIdx.x * 64;

    float c[2][4][4];
    #pragma unroll
    for (int mt = 0; mt < 2; mt++)
        #pragma unroll
        for (int nt = 0; nt < 4; nt++)
            #pragma unroll
            for (int i = 0; i < 4; i++) c[mt][nt][i] = 0.f;

    float4 pa[4], pb[2];
    // prefetch chunk 0
    #pragma unroll
    for (int j = 0; j < 4; j++) {
        int idx = tid + j * 256, row = idx >> 3, kq = idx & 7;
        pa[j] = *(const float4*)(Ab + (size_t)row * Kd + kq * 4);
    }
    #pragma unroll
    for (int j = 0; j < 2; j++) {
        int idx = tid + j * 256, row = idx >> 4, cq = idx & 15;
        pb[j] = *(const float4*)(Bb + (size_t)row * Nc + cq * 4);
    }
    #pragma unroll
    for (int j = 0; j < 4; j++) {
        int idx = tid + j * 256, row = idx >> 3, kq = idx & 7;
        *(float4*)&As[row * ASTR + kq * 4] = pa[j];
    }
    #pragma unroll
    for (int j = 0; j < 2; j++) {
        int idx = tid + j * 256, row = idx >> 4, cq = idx & 15;
        *(float4*)&Bs[row * BSTR + cq * 4] = pb[j];
    }
    __syncthreads();

    int nch = Kd >> 5;
    for (int ch = 0; ch < nch; ch++) {
        int buf = ch & 1;
        if (ch + 1 < nch) {
            int k0 = (ch + 1) * 32;
            #pragma unroll
            for (int j = 0; j < 4; j++) {
                int idx = tid + j * 256, row = idx >> 3, kq = idx & 7;
                pa[j] = *(const float4*)(Ab + (size_t)row * Kd + k0 + kq * 4);
            }
            #pragma unroll
            for (int j = 0; j < 2; j++) {
                int idx = tid + j * 256, row = idx >> 4, cq = idx & 15;
                pb[j] = *(const float4*)(Bb + (size_t)(k0 + row) * Nc + cq * 4);
            }
        }
        const float* Abs = As + buf * A_BUF;
        const float* Bbs = Bs + buf * B_BUF;
        #pragma unroll
        for (int ks = 0; ks < 4; ks++) {
            int k = ks * 8;
            unsigned ahi[2][4], alo[2][4], bhi[4][2], blo[4][2];
            #pragma unroll
            for (int mt = 0; mt < 2; mt++) {
                int rb = mw + mt * 16 + g;
                float a0 = Abs[rb * ASTR + k + tig];
                float a1 = Abs[(rb + 8) * ASTR + k + tig];
                float a2 = Abs[rb * ASTR + k + tig + 4];
                float a3 = Abs[(rb + 8) * ASTR + k + tig + 4];
                tf32_split(a0, ahi[mt][0], alo[mt][0]);
                tf32_split(a1, ahi[mt][1], alo[mt][1]);
                tf32_split(a2, ahi[mt][2], alo[mt][2]);
                tf32_split(a3, ahi[mt][3], alo[mt][3]);
            }
            #pragma unroll
            for (int nt = 0; nt < 4; nt++) {
                int cb = nw + nt * 8 + g;
                float b0 = Bbs[(k + tig) * BSTR + cb];
                float b1 = Bbs[(k + tig + 4) * BSTR + cb];
                tf32_split(b0, bhi[nt][0], blo[nt][0]);
                tf32_split(b1, bhi[nt][1], blo[nt][1]);
            }
            #pragma unroll
            for (int mt = 0; mt < 2; mt++)
                #pragma unroll
                for (int nt = 0; nt < 4; nt++) {
                    mma8(c[mt][nt], alo[mt], bhi[nt]);
                    mma8(c[mt][nt], ahi[mt], blo[nt]);
                    mma8(c[mt][nt], ahi[mt], bhi[nt]);
                }
        }
        if (ch + 1 < nch) {
            float* Ad = As + (buf ^ 1) * A_BUF;
            float* Bd = Bs + (buf ^ 1) * B_BUF;
            #pragma unroll
            for (int j = 0; j < 4; j++) {
                int idx = tid + j * 256, row = idx >> 3, kq = idx & 7;
                *(float4*)&Ad[row * ASTR + kq * 4] = pa[j];
            }
            #pragma unroll
            for (int j = 0; j < 2; j++) {
                int idx = tid + j * 256, row = idx >> 4, cq = idx & 15;
                *(float4*)&Bd[row * BSTR + cq * 4] = pb[j];
            }
            __syncthreads();
        }
    }

    int row0 = blockIdx.y * 128 + mw;
    int col0 = blockIdx.x * 64 + nw;
    #pragma unroll
    for (int mt = 0; mt < 2; mt++)
        #pragma unroll
        for (int nt = 0; nt < 4; nt++) {
            int r = row0 + mt * 16 + g;
            int cc = col0 + nt * 8 + 2 * tig;
            *(float2*)&C[(size_t)r * Nc + cc] = make_float2(c[mt][nt][0], c[mt][nt][1]);
            *(float2*)&C[(size_t)(r + 8) * Nc + cc] = make_float2(c[mt][nt][2], c[mt][nt][3]);
        }
}

// ---------------- fully fused subgraph CSR build (block per subgraph) ----------------
__global__ void k_csr_sub(const int* __restrict__ sei) {
    __shared__ int cnt[1024];
    __shared__ int cur[1024];
    int s = blockIdx.x, t = threadIdx.x;
    cnt[t] = 0;
    __syncthreads();
    const int* base = sei + s * 2 * ESUB;
    #pragma unroll
    for (int e = t; e < ESUB; e += 1024)
        atomicAdd(&cnt[base[ESUB + e]], 1);
    __syncthreads();
    int v = cnt[t];
    cur[t] = v; __syncthreads();
    #pragma unroll
    for (int o = 1; o < 1024; o <<= 1) {
        int x = (t >= o) ? cur[t - o] : 0;
        __syncthreads();
        cur[t] += x;
        __syncthreads();
    }
    int loc = cur[t] - v;
    g_stS[s * NSUB + t]  = s * ESUB + loc;
    g_cntS[s * NSUB + t] = v;
    g_dinv[s * NSUB + t] = rsqrtf((float)v + 1.f);
    __syncthreads();
    cur[t] = loc;
    __syncthreads();
    #pragma unroll
    for (int e = t; e < ESUB; e += 1024) {
        int src = base[e], dst = base[ESUB + e];
        int p = atomicAdd(&cur[dst], 1);
        g_adjS[s * ESUB + p] = src;
    }
}

// ---------------- generic 65536-entry scan (64 blocks x 1024) ----------------
__global__ void k_hist32(const int* __restrict__ key, int* cnt, int n) {
    int i = blockIdx.x * blockDim.x + threadIdx.x;
    if (i < n) atomicAdd(&cnt[key[i]], 1);
}
__global__ void k_scan_block(const int* __restrict__ cnt, int* start, int* bsum) {
    __shared__ int sh[1024];
    int b = blockIdx.x, t = threadIdx.x, i = b * 1024 + t;
    int v = cnt[i];
    sh[t] = v; __syncthreads();
    for (int o = 1; o < 1024; o <<= 1) {
        int x = (t >= o) ? sh[t - o] : 0;
        __syncthreads();
        sh[t] += x;
        __syncthreads();
    }
    start[i] = sh[t] - v;
    if (t == 1023) bsum[b] = sh[t];
}
__global__ void k_scan_top(int* bsum, int n) {
    int acc = 0;
    for (int i = 0; i < n; i++) { int v = bsum[i]; bsum[i] = acc; acc += v; }
}
__global__ void k_scan_add(int* start, int* cur, const int* __restrict__ cnt,
                           const int* __restrict__ bsum, float* dinv) {
    int i = blockIdx.x * blockDim.x + threadIdx.x;
    if (i >= NGLOB) return;
    int v = start[i] + bsum[i >> 10];
    start[i] = v; cur[i] = v;
    if (dinv) dinv[i] = rsqrtf((float)cnt[i] + 1.f);
}
__global__ void k_adj_glob(const int* __restrict__ eidx) {
    int e = blockIdx.x * blockDim.x + threadIdx.x;
    if (e >= EGLOB) return;
    g_adjG[atomicAdd(&g_curG[eidx[EGLOB + e]], 1)] = eidx[e];
}
__global__ void k_adj_x(const int* __restrict__ sorig) {
    int i = blockIdx.x * blockDim.x + threadIdx.x;
    if (i >= S * NSUB) return;
    g_adjX[atomicAdd(&g_curX[sorig[i]], 1)] = i;
}

// ---------------- fused GCN layer (subgraph, F=128): warp per node ----------------
// DOT: also emit hp[w] = relu_row . Wp (fuses the SAGPool scorer projection)
template<bool RELU, bool DOT>
__global__ void k_gcn_sub(const float* __restrict__ h, const float* __restrict__ bias,
                          float* __restrict__ outp,
                          const float* __restrict__ Wp, float* __restrict__ hp) {
    int w = (blockIdx.x * blockDim.x + threadIdx.x) >> 5;
    int lane = threadIdx.x & 31;
    if (w >= S * NSUB) return;
    int s = w >> 10;
    int st = g_stS[w], cn = g_cntS[w];
    float4 acc = {0.f, 0.f, 0.f, 0.f};
    for (int base = 0; base < cn; base += 32) {
        int id = (base + lane < cn) ? g_adjS[st + base + lane] : 0;
        int m = min(32, cn - base);
        for (int k = 0; k < m; k++) {
            int src = s * NSUB + __shfl_sync(0xffffffffu, id, k);
            float c = __ldg(&g_dinv[src]);
            float4 v = __ldg((const float4*)(h + (size_t)src * F) + lane);
            acc.x += v.x * c; acc.y += v.y * c; acc.z += v.z * c; acc.w += v.w * c;
        }
    }
    float d = g_dinv[w];
    float4 hv = __ldg((const float4*)(h + (size_t)w * F) + lane);
    float4 bv = __ldg((const float4*)bias + lane);
    float4 r;
    r.x = acc.x * d + hv.x * d * d + bv.x;
    r.y = acc.y * d + hv.y * d * d + bv.y;
    r.z = acc.z * d + hv.z * d * d + bv.z;
    r.w = acc.w * d + hv.w * d * d + bv.w;
    if (RELU) {
        r.x = fmaxf(r.x, 0.f); r.y = fmaxf(r.y, 0.f);
        r.z = fmaxf(r.z, 0.f); r.w = fmaxf(r.w, 0.f);
    }
    ((float4*)(outp + (size_t)w * F))[lane] = r;
    if (DOT) {
        float4 wv = __ldg((const float4*)Wp + lane);
        float dv = r.x * wv.x + r.y * wv.y + r.z * wv.z + r.w * wv.w;
        #pragma unroll
        for (int o = 16; o; o >>= 1) dv += __shfl_xor_sync(0xffffffffu, dv, o);
        if (lane == 0) hp[w] = dv;
    }
}

// ---------------- scorer GCN (1-dim) ----------------
__global__ void k_score_csr(const float* __restrict__ hp, const float* __restrict__ bp,
                            float* __restrict__ score) {
    int n = blockIdx.x * blockDim.x + threadIdx.x;
    if (n >= S * NSUB) return;
    int s = n >> 10;
    int st = g_stS[n], cn = g_cntS[n];
    float acc = 0.f;
    for (int k = 0; k < cn; k++) {
        int src = s * NSUB + g_adjS[st + k];
        acc += hp[src] * g_dinv[src];
    }
    float d = g_dinv[n];
    score[n] = acc * d + hp[n] * d * d + bp[0];
}

// ---------------- pooled graph degree ----------------
__global__ void k_deg_pool_csr() {
    int n = blockIdx.x * blockDim.x + threadIdx.x;
    if (n >= S * NSUB) return;
    int pd = g_pos[n];
    if (pd < 0) return;
    int s = n >> 10;
    int st = g_stS[n], cn = g_cntS[n], c = 0;
    for (int k = 0; k < cn; k++)
        if (g_pos[s * NSUB + g_adjS[st + k]] >= 0) c++;
    g_dinv2[s * KPOOL + pd] = rsqrtf((float)c + 1.f);
}

// ---------------- pooled GCN layer: warp per original node ----------------
__global__ void k_gcn_pool(const float* __restrict__ hpool, const float* __restrict__ bsc,
                           float* __restrict__ xsub) {
    int w = (blockIdx.x * blockDim.x + threadIdx.x) >> 5;
    int lane = threadIdx.x & 31;
    if (w >= S * NSUB) return;
    int pd = g_pos[w];
    if (pd < 0) return;
    int s = w >> 10;
    int st = g_stS[w], cn = g_cntS[w];
    float4 acc = {0.f, 0.f, 0.f, 0.f};
    for (int base = 0; base < cn; base += 32) {
        int id = (base + lane < cn) ? g_adjS[st + base + lane] : 0;
        int m = min(32, cn - base);
        for (int k = 0; k < m; k++) {
            int srcl = __shfl_sync(0xffffffffu, id, k);
            int ps = g_pos[s * NSUB + srcl];
            if (ps < 0) continue;
            int row = s * KPOOL + ps;
            float c = __ldg(&g_dinv2[row]);
            float4 v = __ldg((const float4*)(hpool + (size_t)row * F) + lane);
            acc.x += v.x * c; acc.y += v.y * c; acc.z += v.z * c; acc.w += v.w * c;
        }
    }
    int prow = s * KPOOL + pd;
    float d = g_dinv2[prow];
    float4 hv = __ldg((const float4*)(hpool + (size_t)prow * F) + lane);
    float4 bv = __ldg((const float4*)bsc + lane);
    float4 r;
    r.x = fmaxf(acc.x * d + hv.x * d * d + bv.x, 0.f);
    r.y = fmaxf(acc.y * d + hv.y * d * d + bv.y, 0.f);
    r.z = fmaxf(acc.z * d + hv.z * d * d + bv.z, 0.f);
    r.w = fmaxf(acc.w * d + hv.w * d * d + bv.w, 0.f);
    ((float4*)(xsub + (size_t)prow * F))[lane] = r;
}

// ---------------- top-512 of 1024 per subgraph ----------------
__global__ void k_topk() {
    __shared__ float vals[1024];
    __shared__ int   idxs[1024];
    int s = blockIdx.x, t = threadIdx.x;  // 512 threads
    vals[t]       = g_score[s * NSUB + t];       idxs[t]       = t;
    vals[t + 512] = g_score[s * NSUB + t + 512]; idxs[t + 512] = t + 512;
    g_pos[s * NSUB + t] = -1;
    g_pos[s * NSUB + t + 512] = -1;
    __syncthreads();
    for (int k2 = 2; k2 <= 1024; k2 <<= 1) {
        for (int j = k2 >> 1; j > 0; j >>= 1) {
            int i = ((t & ~(j - 1)) << 1) | (t & (j - 1));
            int ixj = i | j;
            bool ascend = ((i & k2) != 0);
            float vi = vals[i], vj = vals[ixj];
            bool sw = ascend ? (vi > vj) : (vi < vj);
            if (sw) {
                vals[i] = vj; vals[ixj] = vi;
                int tmp = idxs[i]; idxs[i] = idxs[ixj]; idxs[ixj] = tmp;
            }
            __syncthreads();
        }
    }
    int selidx = idxs[t];
    g_sel[s * KPOOL + t] = selidx;
    g_pos[s * NSUB + selidx] = t;
}

__global__ void k_xpool() {
    int i = blockIdx.x * blockDim.x + threadIdx.x;
    if (i >= S * KPOOL * F) return;
    int c = i & (F - 1);
    int rj = i >> 7;
    int s = rj >> 9;
    int sel = g_sel[rj];
    float gate = tanhf(g_score[s * NSUB + sel]);
    g_xpool[i] = g_x1[(size_t)(s * NSUB + sel) * F + c] * gate;
}

// ---------------- subgraph embedding: max+mean (512 thr/block) ----------------
__global__ void k_emb() {
    __shared__ float smx1[512], ssm1[512], smx2[512], ssm2[512];
    int s = blockIdx.x, t = threadIdx.x;
    int c = t & 127, part = t >> 7;
    const float* xp = g_xpool + (size_t)s * KPOOL * F + c;
    const float* xs = g_xsub  + (size_t)s * KPOOL * F + c;
    float mx1 = -INFINITY, sm1 = 0.f, mx2 = -INFINITY, sm2 = 0.f;
    for (int j = part; j < KPOOL; j += 4) {
        float v1 = xp[(size_t)j * F]; mx1 = fmaxf(mx1, v1); sm1 += v1;
        float v2 = xs[(size_t)j * F]; mx2 = fmaxf(mx2, v2); sm2 += v2;
    }
    smx1[t] = mx1; ssm1[t] = sm1; smx2[t] = mx2; ssm2[t] = sm2;
    __syncthreads();
    if (part == 0) {
        #pragma unroll
        for (int p = 1; p < 4; p++) {
            mx1 = fmaxf(mx1, smx1[p * 128 + c]); sm1 += ssm1[p * 128 + c];
            mx2 = fmaxf(mx2, smx2[p * 128 + c]); sm2 += ssm2[p * 128 + c];
        }
        g_subemb[s * 256 + c]       = mx1 + mx2;
        g_subemb[s * 256 + 128 + c] = (sm1 + sm2) * (1.f / KPOOL);
    }
}

// ---------------- small gemm (collapsed attention) ----------------
__global__ void k_small_gemm(const float* __restrict__ X, const float* __restrict__ W,
                             const float* __restrict__ b, float* __restrict__ out,
                             int ldw, int coloff, int Kd, int Ncols) {
    __shared__ float xs[256];
    int s = blockIdx.x;
    for (int i = threadIdx.x; i < Kd; i += blockDim.x) xs[i] = X[s * Kd + i];
    __syncthreads();
    int j = threadIdx.x;
    float acc = b[coloff + j];
    for (int k = 0; k < Kd; k++) acc += xs[k] * W[k * ldw + coloff + j];
    out[s * Ncols + j] = acc;
}

// ---------------- gather combined rows -> global embedding (in out buffer) ----------------
__global__ void k_gather_emb(float* __restrict__ gemb) {
    int n = blockIdx.x;
    int c = threadIdx.x;      // 384
    int st = g_stX[n], cn = g_cntX[n];
    float acc = 0.f;
    for (int k = 0; k < cn; k++) {
        int row = g_adjX[st + k];
        int s = row >> 10;
        acc += (c < F) ? g_x2[(size_t)row * F + c] : g_att[s * 256 + (c - F)];
    }
    gemb[(size_t)n * 384 + c] = acc;
}

// ---------------- fused final GCN agg + log_softmax: warp per global node ----------------
__global__ void k_final(const float* __restrict__ hf, const float* __restrict__ bf,
                        float* __restrict__ out) {
    int w = (blockIdx.x * blockDim.x + threadIdx.x) >> 5;
    int lane = threadIdx.x & 31;
    if (w >= NGLOB) return;
    int st = g_stG[w], cn = g_cntG[w];
    float a = 0.f, b = 0.f;
    for (int base = 0; base < cn; base += 32) {
        int id = (base + lane < cn) ? g_adjG[st + base + lane] : 0;
        int m = min(32, cn - base);
        for (int k = 0; k < m; k++) {
            int src = __shfl_sync(0xffffffffu, id, k);
            float c = __ldg(&g_dinvf[src]);
            a += __ldg(&hf[(size_t)src * 64 + lane])      * c;
            b += __ldg(&hf[(size_t)src * 64 + 32 + lane]) * c;
        }
    }
    float d = g_dinvf[w];
    a = a * d + hf[(size_t)w * 64 + lane]      * d * d + bf[lane];
    b = b * d + hf[(size_t)w * 64 + 32 + lane] * d * d + bf[32 + lane];
    float m = fmaxf(a, b);
    #pragma unroll
    for (int o = 16; o; o >>= 1) m = fmaxf(m, __shfl_xor_sync(0xffffffffu, m, o));
    float ssum = expf(a - m) + expf(b - m);
    #pragma unroll
    for (int o = 16; o; o >>= 1) ssum += __shfl_xor_sync(0xffffffffu, ssum, o);
    float ls = m + logf(ssum);
    out[(size_t)w * 64 + lane]      = a - ls;
    out[(size_t)w * 64 + 32 + lane] = b - ls;
}

// ========================= host orchestration =========================
extern "C" void kernel_launch(void* const* d_in, const int* in_sizes, int n_in,
                              void* d_out, int out_size) {
    const float* sub_x = (const float*)d_in[0];
    const int*   sei   = (const int*)d_in[1];
    const int*   sorig = (const int*)d_in[2];
    const int*   eidx  = (const int*)d_in[3];
    const float* W1  = (const float*)d_in[4];
    const float* b1  = (const float*)d_in[5];
    const float* W2  = (const float*)d_in[6];
    const float* b2  = (const float*)d_in[7];
    const float* Wp  = (const float*)d_in[8];
    const float* bp  = (const float*)d_in[9];
    const float* Wsc = (const float*)d_in[10];
    const float* bsc = (const float*)d_in[11];
    const float* Wqkv= (const float*)d_in[12];
    const float* bqkv= (const float*)d_in[13];
    const float* Wo  = (const float*)d_in[14];
    const float* bo  = (const float*)d_in[15];
    const float* Wf  = (const float*)d_in[16];
    const float* bf  = (const float*)d_in[17];
    float* out = (float*)d_out;

    float *h, *x1, *x2, *hp, *score, *xpool, *hpool, *xsub, *subemb, *v, *att, *hf;
    float *dinvf;
    int *cntG, *cntX, *stG, *stX, *curG, *curX, *bsumG, *bsumX;
    cudaGetSymbolAddress((void**)&h, g_h);
    cudaGetSymbolAddress((void**)&x1, g_x1);
    cudaGetSymbolAddress((void**)&x2, g_x2);
    cudaGetSymbolAddress((void**)&hp, g_hp);
    cudaGetSymbolAddress((void**)&score, g_score);
    cudaGetSymbolAddress((void**)&xpool, g_xpool);
    cudaGetSymbolAddress((void**)&hpool, g_hpool);
    cudaGetSymbolAddress((void**)&xsub, g_xsub);
    cudaGetSymbolAddress((void**)&subemb, g_subemb);
    cudaGetSymbolAddress((void**)&v, g_v);
    cudaGetSymbolAddress((void**)&att, g_att);
    cudaGetSymbolAddress((void**)&hf, g_hf);
    cudaGetSymbolAddress((void**)&dinvf, g_dinvf);
    cudaGetSymbolAddress((void**)&cntG, g_cntG);
    cudaGetSymbolAddress((void**)&cntX, g_cntX);
    cudaGetSymbolAddress((void**)&stG, g_stG);
    cudaGetSymbolAddress((void**)&stX, g_stX);
    cudaGetSymbolAddress((void**)&curG, g_curG);
    cudaGetSymbolAddress((void**)&curX, g_curX);
    cudaGetSymbolAddress((void**)&bsumG, g_bsumG);
    cudaGetSymbolAddress((void**)&bsumX, g_bsumX);

    float* gemb = out + (size_t)NGLOB * NCLS;

    cudaFuncSetAttribute(tgemm, cudaFuncAttributeMaxDynamicSharedMemorySize, TG_SMEM);

    const int T = 256;
    const int ROWS = S * NSUB;          // 65536

    // --- subgraph CSR (single fused kernel) ---
    k_csr_sub<<<S, 1024>>>(sei);

    // --- global / scatter CSRs ---
    k_zero<<<NGLOB / T, T>>>(cntG, NGLOB);
    k_zero<<<NGLOB / T, T>>>(cntX, NGLOB);

    k_hist32<<<EGLOB / T, T>>>(eidx + EGLOB, cntG, EGLOB);
    k_scan_block<<<64, 1024>>>(cntG, stG, bsumG);
    k_scan_top<<<1, 1>>>(bsumG, 64);
    k_scan_add<<<NGLOB / T, T>>>(stG, curG, cntG, bsumG, dinvf);
    k_adj_glob<<<EGLOB / T, T>>>(eidx);

    k_hist32<<<ROWS / T, T>>>(sorig, cntX, ROWS);
    k_scan_block<<<64, 1024>>>(cntX, stX, bsumX);
    k_scan_top<<<1, 1>>>(bsumX, 64);
    k_scan_add<<<NGLOB / T, T>>>(stX, curX, cntX, bsumX, nullptr);
    k_adj_x<<<ROWS / T, T>>>(sorig);

    // --- GCN1 (fused scorer dot) / GCN2 ---
    tgemm<<<dim3(2, ROWS / 128), 256, TG_SMEM>>>(sub_x, W1, h, ROWS, F, F);
    k_gcn_sub<true, true><<<ROWS * 32 / T, T>>>(h, b1, x1, Wp, hp);
    tgemm<<<dim3(2, ROWS / 128), 256, TG_SMEM>>>(x1, W2, h, ROWS, F, F);
    k_gcn_sub<true, false><<<ROWS * 32 / T, T>>>(h, b2, x2, nullptr, nullptr);

    // --- scorer + top-k pooling ---
    k_score_csr<<<ROWS / T, T>>>(hp, bp, score);
    k_topk<<<S, 512>>>();
    k_xpool<<<S * KPOOL * F / T, T>>>();

    // --- pooled GCN ---
    k_deg_pool_csr<<<ROWS / T, T>>>();
    tgemm<<<dim3(2, (S * KPOOL) / 128), 256, TG_SMEM>>>(xpool, Wsc, hpool, S * KPOOL, F, F);
    k_gcn_pool<<<ROWS * 32 / T, T>>>(hpool, bsc, xsub);

    // --- subgraph embeddings + collapsed attention ---
    k_emb<<<S, 512>>>();
    k_small_gemm<<<S, 256>>>(subemb, Wqkv, bqkv, v, 768, 512, 256, 256);
    k_small_gemm<<<S, 256>>>(v, Wo, bo, att, 256, 0, 256, 256);

    // --- gather into global embedding (written straight into out) ---
    k_gather_emb<<<NGLOB, 384>>>(gemb);

    // --- final GCN + log_softmax (fused) ---
    tgemm<<<dim3(1, NGLOB / 128), 256, TG_SMEM>>>(gemb, Wf, hf, NGLOB, 384, 64);
    k_final<<<NGLOB * 32 / T, T>>>(hf, bf, out);
}

// round 5
// speedup vs baseline: 2.7046x; 1.0758x over previous
#include <cuda_runtime.h>
#include <math.h>

#define S      64
#define NSUB   1024
#define ESUB   16384
#define NGLOB  65536
#define EGLOB  1048576
#define F      128
#define KPOOL  512
#define NCLS   64

// ---------------- scratch (device globals) ----------------
__device__ float g_h    [S*NSUB*F];
__device__ float g_x1   [S*NSUB*F];
__device__ float g_x2   [S*NSUB*F];
__device__ float g_hp   [S*NSUB];          // pre-scaled scorer proj (hp*dinv)
__device__ float g_score[S*NSUB];
__device__ int   g_sel  [S*KPOOL];
__device__ int   g_pos  [S*NSUB];
__device__ float g_xpool[S*KPOOL*F];
__device__ float g_hpool[S*KPOOL*F];
__device__ float g_xsub [S*KPOOL*F];
__device__ float g_subemb[S*256];
__device__ float g_att  [S*256];
__device__ float g_hf   [NGLOB*64];

__device__ float g_dinv [S*NSUB];
__device__ float g_dinv2[S*KPOOL];
__device__ float g_dinvf[NGLOB];

// CSR: subgraph edges (by dst, per subgraph slab)
__device__ int g_cntS [S*NSUB];
__device__ int g_stS  [S*NSUB];
__device__ int g_adjS [S*ESUB];
// CSR: global edges (by dst)
__device__ int g_cntG [NGLOB];
__device__ int g_stG  [NGLOB];
__device__ int g_curG [NGLOB];
__device__ int g_adjG [EGLOB];
// CSR: scatter rows (by sub_orig_idx)
__device__ int g_cntX [NGLOB];
__device__ int g_stX  [NGLOB];
__device__ int g_curX [NGLOB];
__device__ int g_adjX [S*NSUB];
__device__ int g_bsumG[64];
__device__ int g_bsumX[64];

// ---------------- utility ----------------
__global__ void k_zero2(int* p0, int* p1, int n) {
    int i = blockIdx.x * blockDim.x + threadIdx.x;
    if (i < n) { p0[i] = 0; p1[i] = 0; }
}

// ============ GEMM: tensor-core 3xTF32 (mma.sync.m16n8k8) ============
// C[M,Nc] = (A[M,K] @ B[K,Nc]) * rscale[row]   (rscale optional)
#define ASTR 36
#define BSTR 72
#define A_BUF (128 * ASTR)
#define B_BUF (32 * BSTR)
#define TG_SMEM ((2 * A_BUF + 2 * B_BUF) * 4)

__device__ __forceinline__ void tf32_split(float a, unsigned& hi, unsigned& lo) {
    asm("cvt.rna.tf32.f32 %0, %1;" : "=r"(hi) : "f"(a));
    float r = a - __uint_as_float(hi);
    asm("cvt.rna.tf32.f32 %0, %1;" : "=r"(lo) : "f"(r));
}
__device__ __forceinline__ void mma8(float c[4], const unsigned a[4], const unsigned b[2]) {
    asm("mma.sync.aligned.m16n8k8.row.col.f32.tf32.tf32.f32 "
        "{%0,%1,%2,%3}, {%4,%5,%6,%7}, {%8,%9}, {%0,%1,%2,%3};"
        : "+f"(c[0]), "+f"(c[1]), "+f"(c[2]), "+f"(c[3])
        : "r"(a[0]), "r"(a[1]), "r"(a[2]), "r"(a[3]), "r"(b[0]), "r"(b[1]));
}

__global__ void __launch_bounds__(256, 2)
tgemm(const float* __restrict__ A, const float* __restrict__ B,
      float* __restrict__ C, int M, int Kd, int Nc,
      const float* __restrict__ rscale) {
    extern __shared__ float sm[];
    float* As = sm;
    float* Bs = sm + 2 * A_BUF;

    int tid = threadIdx.x;
    int wid = tid >> 5, lane = tid & 31;
    int g = lane >> 2, tig = lane & 3;
    int wr = wid & 3, wc = wid >> 2;
    int mw = wr * 32, nw = wc * 32;
    const float* Ab = A + (size_t)blockIdx.y * 128 * Kd;
    const float* Bb = B + blockIdx.x * 64;

    float c[2][4][4];
    #pragma unroll
    for (int mt = 0; mt < 2; mt++)
        #pragma unroll
        for (int nt = 0; nt < 4; nt++)
            #pragma unroll
            for (int i = 0; i < 4; i++) c[mt][nt][i] = 0.f;

    float4 pa[4], pb[2];
    #pragma unroll
    for (int j = 0; j < 4; j++) {
        int idx = tid + j * 256, row = idx >> 3, kq = idx & 7;
        pa[j] = *(const float4*)(Ab + (size_t)row * Kd + kq * 4);
    }
    #pragma unroll
    for (int j = 0; j < 2; j++) {
        int idx = tid + j * 256, row = idx >> 4, cq = idx & 15;
        pb[j] = *(const float4*)(Bb + (size_t)row * Nc + cq * 4);
    }
    #pragma unroll
    for (int j = 0; j < 4; j++) {
        int idx = tid + j * 256, row = idx >> 3, kq = idx & 7;
        *(float4*)&As[row * ASTR + kq * 4] = pa[j];
    }
    #pragma unroll
    for (int j = 0; j < 2; j++) {
        int idx = tid + j * 256, row = idx >> 4, cq = idx & 15;
        *(float4*)&Bs[row * BSTR + cq * 4] = pb[j];
    }
    __syncthreads();

    int nch = Kd >> 5;
    for (int ch = 0; ch < nch; ch++) {
        int buf = ch & 1;
        if (ch + 1 < nch) {
            int k0 = (ch + 1) * 32;
            #pragma unroll
            for (int j = 0; j < 4; j++) {
                int idx = tid + j * 256, row = idx >> 3, kq = idx & 7;
                pa[j] = *(const float4*)(Ab + (size_t)row * Kd + k0 + kq * 4);
            }
            #pragma unroll
            for (int j = 0; j < 2; j++) {
                int idx = tid + j * 256, row = idx >> 4, cq = idx & 15;
                pb[j] = *(const float4*)(Bb + (size_t)(k0 + row) * Nc + cq * 4);
            }
        }
        const float* Abs = As + buf * A_BUF;
        const float* Bbs = Bs + buf * B_BUF;
        #pragma unroll
        for (int ks = 0; ks < 4; ks++) {
            int k = ks * 8;
            unsigned ahi[2][4], alo[2][4], bhi[4][2], blo[4][2];
            #pragma unroll
            for (int mt = 0; mt < 2; mt++) {
                int rb = mw + mt * 16 + g;
                float a0 = Abs[rb * ASTR + k + tig];
                float a1 = Abs[(rb + 8) * ASTR + k + tig];
                float a2 = Abs[rb * ASTR + k + tig + 4];
                float a3 = Abs[(rb + 8) * ASTR + k + tig + 4];
                tf32_split(a0, ahi[mt][0], alo[mt][0]);
                tf32_split(a1, ahi[mt][1], alo[mt][1]);
                tf32_split(a2, ahi[mt][2], alo[mt][2]);
                tf32_split(a3, ahi[mt][3], alo[mt][3]);
            }
            #pragma unroll
            for (int nt = 0; nt < 4; nt++) {
                int cb = nw + nt * 8 + g;
                float b0 = Bbs[(k + tig) * BSTR + cb];
                float b1 = Bbs[(k + tig + 4) * BSTR + cb];
                tf32_split(b0, bhi[nt][0], blo[nt][0]);
                tf32_split(b1, bhi[nt][1], blo[nt][1]);
            }
            #pragma unroll
            for (int mt = 0; mt < 2; mt++)
                #pragma unroll
                for (int nt = 0; nt < 4; nt++) {
                    mma8(c[mt][nt], alo[mt], bhi[nt]);
                    mma8(c[mt][nt], ahi[mt], blo[nt]);
                    mma8(c[mt][nt], ahi[mt], bhi[nt]);
                }
        }
        if (ch + 1 < nch) {
            float* Ad = As + (buf ^ 1) * A_BUF;
            float* Bd = Bs + (buf ^ 1) * B_BUF;
            #pragma unroll
            for (int j = 0; j < 4; j++) {
                int idx = tid + j * 256, row = idx >> 3, kq = idx & 7;
                *(float4*)&Ad[row * ASTR + kq * 4] = pa[j];
            }
            #pragma unroll
            for (int j = 0; j < 2; j++) {
                int idx = tid + j * 256, row = idx >> 4, cq = idx & 15;
                *(float4*)&Bd[row * BSTR + cq * 4] = pb[j];
            }
            __syncthreads();
        }
    }

    int row0 = blockIdx.y * 128 + mw;
    int col0 = blockIdx.x * 64 + nw;
    #pragma unroll
    for (int mt = 0; mt < 2; mt++) {
        int r = row0 + mt * 16 + g;
        float s0 = rscale ? rscale[r] : 1.f;
        float s1 = rscale ? rscale[r + 8] : 1.f;
        #pragma unroll
        for (int nt = 0; nt < 4; nt++) {
            int cc = col0 + nt * 8 + 2 * tig;
            *(float2*)&C[(size_t)r * Nc + cc] =
                make_float2(c[mt][nt][0] * s0, c[mt][nt][1] * s0);
            *(float2*)&C[(size_t)(r + 8) * Nc + cc] =
                make_float2(c[mt][nt][2] * s1, c[mt][nt][3] * s1);
        }
    }
}

// ---------------- fully fused subgraph CSR build (block per subgraph) ----------------
__global__ void k_csr_sub(const int* __restrict__ sei) {
    __shared__ int cnt[1024];
    __shared__ int cur[1024];
    int s = blockIdx.x, t = threadIdx.x;
    cnt[t] = 0;
    __syncthreads();
    const int* base = sei + s * 2 * ESUB;
    #pragma unroll
    for (int e = t; e < ESUB; e += 1024)
        atomicAdd(&cnt[base[ESUB + e]], 1);
    __syncthreads();
    int v = cnt[t];
    cur[t] = v; __syncthreads();
    #pragma unroll
    for (int o = 1; o < 1024; o <<= 1) {
        int x = (t >= o) ? cur[t - o] : 0;
        __syncthreads();
        cur[t] += x;
        __syncthreads();
    }
    int loc = cur[t] - v;
    g_stS[s * NSUB + t]  = s * ESUB + loc;
    g_cntS[s * NSUB + t] = v;
    g_dinv[s * NSUB + t] = rsqrtf((float)v + 1.f);
    __syncthreads();
    cur[t] = loc;
    __syncthreads();
    #pragma unroll
    for (int e = t; e < ESUB; e += 1024) {
        int src = base[e], dst = base[ESUB + e];
        int p = atomicAdd(&cur[dst], 1);
        g_adjS[s * ESUB + p] = src;
    }
}

// ---------------- fused global + scatter CSR builds ----------------
__global__ void k_hist_both(const int* __restrict__ eidx, const int* __restrict__ sorig) {
    int i = blockIdx.x * blockDim.x + threadIdx.x;
    if (i < EGLOB) atomicAdd(&g_cntG[eidx[EGLOB + i]], 1);
    else {
        int j = i - EGLOB;
        if (j < S * NSUB) atomicAdd(&g_cntX[sorig[j]], 1);
    }
}
__global__ void k_scan_block2() {
    __shared__ int sh[1024];
    int b = blockIdx.x, t = threadIdx.x;
    const int* cnt; int* start; int* bsum; int i;
    if (b < 64) { cnt = g_cntG; start = g_stG; bsum = g_bsumG; i = b * 1024 + t; }
    else        { cnt = g_cntX; start = g_stX; bsum = g_bsumX; i = (b - 64) * 1024 + t; }
    int v = cnt[i];
    sh[t] = v; __syncthreads();
    for (int o = 1; o < 1024; o <<= 1) {
        int x = (t >= o) ? sh[t - o] : 0;
        __syncthreads();
        sh[t] += x;
        __syncthreads();
    }
    start[i] = sh[t] - v;
    if (t == 1023) bsum[b < 64 ? b : b - 64] = sh[t];
}
__global__ void k_scan_top2() {
    int t = threadIdx.x;
    if (t == 0) { int a = 0; for (int i = 0; i < 64; i++) { int v = g_bsumG[i]; g_bsumG[i] = a; a += v; } }
    if (t == 32){ int a = 0; for (int i = 0; i < 64; i++) { int v = g_bsumX[i]; g_bsumX[i] = a; a += v; } }
}
__global__ void k_scan_add2() {
    int i = blockIdx.x * blockDim.x + threadIdx.x;
    if (i < NGLOB) {
        int v = g_stG[i] + g_bsumG[i >> 10];
        g_stG[i] = v; g_curG[i] = v;
        g_dinvf[i] = rsqrtf((float)g_cntG[i] + 1.f);
    } else {
        int j = i - NGLOB;
        int v = g_stX[j] + g_bsumX[j >> 10];
        g_stX[j] = v; g_curX[j] = v;
    }
}
__global__ void k_adj_both(const int* __restrict__ eidx, const int* __restrict__ sorig) {
    int i = blockIdx.x * blockDim.x + threadIdx.x;
    if (i < EGLOB) g_adjG[atomicAdd(&g_curG[eidx[EGLOB + i]], 1)] = eidx[i];
    else {
        int j = i - EGLOB;
        if (j < S * NSUB) g_adjX[atomicAdd(&g_curX[sorig[j]], 1)] = j;
    }
}

// ---------------- fused GCN layer (subgraph): h pre-scaled by dinv ----------------
// out = dinv[w]*(sum_src hs[src] + hs[w]) + b ; optional relu; optional scorer dot
template<bool RELU, bool DOT>
__global__ void k_gcn_sub(const float* __restrict__ hs, const float* __restrict__ bias,
                          float* __restrict__ outp,
                          const float* __restrict__ Wp, float* __restrict__ hp) {
    int w = (blockIdx.x * blockDim.x + threadIdx.x) >> 5;
    int lane = threadIdx.x & 31;
    if (w >= S * NSUB) return;
    int s = w >> 10;
    int st = g_stS[w], cn = g_cntS[w];
    float4 acc = {0.f, 0.f, 0.f, 0.f};
    for (int base = 0; base < cn; base += 32) {
        int id = (base + lane < cn) ? g_adjS[st + base + lane] : 0;
        int m = min(32, cn - base);
        #pragma unroll 4
        for (int k = 0; k < m; k++) {
            int src = s * NSUB + __shfl_sync(0xffffffffu, id, k);
            float4 v = __ldg((const float4*)(hs + (size_t)src * F) + lane);
            acc.x += v.x; acc.y += v.y; acc.z += v.z; acc.w += v.w;
        }
    }
    float d = g_dinv[w];
    float4 hv = __ldg((const float4*)(hs + (size_t)w * F) + lane);
    float4 bv = __ldg((const float4*)bias + lane);
    float4 r;
    r.x = (acc.x + hv.x) * d + bv.x;
    r.y = (acc.y + hv.y) * d + bv.y;
    r.z = (acc.z + hv.z) * d + bv.z;
    r.w = (acc.w + hv.w) * d + bv.w;
    if (RELU) {
        r.x = fmaxf(r.x, 0.f); r.y = fmaxf(r.y, 0.f);
        r.z = fmaxf(r.z, 0.f); r.w = fmaxf(r.w, 0.f);
    }
    ((float4*)(outp + (size_t)w * F))[lane] = r;
    if (DOT) {
        float4 wv = __ldg((const float4*)Wp + lane);
        float dv = r.x * wv.x + r.y * wv.y + r.z * wv.z + r.w * wv.w;
        #pragma unroll
        for (int o = 16; o; o >>= 1) dv += __shfl_xor_sync(0xffffffffu, dv, o);
        if (lane == 0) hp[w] = dv * d;      // pre-scaled scorer projection
    }
}

// ---------------- scorer GCN (1-dim), hp pre-scaled ----------------
__global__ void k_score_csr(const float* __restrict__ hps, const float* __restrict__ bp,
                            float* __restrict__ score) {
    int n = blockIdx.x * blockDim.x + threadIdx.x;
    if (n >= S * NSUB) return;
    int s = n >> 10;
    int st = g_stS[n], cn = g_cntS[n];
    float acc = 0.f;
    #pragma unroll 4
    for (int k = 0; k < cn; k++)
        acc += hps[s * NSUB + g_adjS[st + k]];
    score[n] = (acc + hps[n]) * g_dinv[n] + bp[0];
}

// ---------------- fused pool: topk + gates + xpool + emb1 + pooled degree ----------------
__global__ void k_pool(const float* __restrict__ x1, float* __restrict__ xpool) {
    __shared__ float vals[1024];
    __shared__ int   idxs[1024];
    __shared__ int   pos[1024];
    __shared__ float gate[512];
    __shared__ float smx[512], ssm[512];
    int s = blockIdx.x, t = threadIdx.x;   // 512 threads

    vals[t]       = g_score[s * NSUB + t];       idxs[t]       = t;
    vals[t + 512] = g_score[s * NSUB + t + 512]; idxs[t + 512] = t + 512;
    pos[t] = -1; pos[t + 512] = -1;
    __syncthreads();
    for (int k2 = 2; k2 <= 1024; k2 <<= 1) {
        for (int j = k2 >> 1; j > 0; j >>= 1) {
            int i = ((t & ~(j - 1)) << 1) | (t & (j - 1));
            int ixj = i | j;
            bool ascend = ((i & k2) != 0);
            float vi = vals[i], vj = vals[ixj];
            bool sw = ascend ? (vi > vj) : (vi < vj);
            if (sw) {
                vals[i] = vj; vals[ixj] = vi;
                int tmp = idxs[i]; idxs[i] = idxs[ixj]; idxs[ixj] = tmp;
            }
            __syncthreads();
        }
    }
    int selidx = idxs[t];
    pos[selidx] = t;
    gate[t] = tanhf(vals[t]);
    g_sel[s * KPOOL + t] = selidx;
    __syncthreads();
    g_pos[s * NSUB + t]       = pos[t];
    g_pos[s * NSUB + t + 512] = pos[t + 512];

    // xpool + emb1 (max/mean over pooled rows)
    int col = t & 127, grp = t >> 7;
    float mx = -INFINITY, sm = 0.f;
    for (int j = grp; j < KPOOL; j += 4) {
        float v = x1[(size_t)(s * NSUB + idxs[j]) * F + col] * gate[j];
        xpool[(size_t)(s * KPOOL + j) * F + col] = v;
        mx = fmaxf(mx, v); sm += v;
    }
    smx[t] = mx; ssm[t] = sm;

    // pooled-graph degrees (uses smem pos)
    for (int n = t; n < NSUB; n += 512) {
        int pd = pos[n];
        if (pd < 0) continue;
        int st = g_stS[s * NSUB + n], cn = g_cntS[s * NSUB + n], c = 0;
        for (int k = 0; k < cn; k++)
            c += (pos[g_adjS[st + k]] >= 0);
        g_dinv2[s * KPOOL + pd] = rsqrtf((float)c + 1.f);
    }
    __syncthreads();
    if (grp == 0) {
        #pragma unroll
        for (int p = 1; p < 4; p++) {
            mx = fmaxf(mx, smx[p * 128 + col]); sm += ssm[p * 128 + col];
        }
        g_subemb[s * 256 + col]       = mx;
        g_subemb[s * 256 + 128 + col] = sm * (1.f / KPOOL);
    }
}

// ---------------- pooled GCN layer (hpool pre-scaled by dinv2) ----------------
__global__ void k_gcn_pool(const float* __restrict__ hpool, const float* __restrict__ bsc,
                           float* __restrict__ xsub) {
    int w = (blockIdx.x * blockDim.x + threadIdx.x) >> 5;
    int lane = threadIdx.x & 31;
    if (w >= S * NSUB) return;
    int pd = g_pos[w];
    if (pd < 0) return;
    int s = w >> 10;
    int st = g_stS[w], cn = g_cntS[w];
    float4 acc = {0.f, 0.f, 0.f, 0.f};
    for (int base = 0; base < cn; base += 32) {
        int id = (base + lane < cn) ? g_adjS[st + base + lane] : 0;
        int m = min(32, cn - base);
        #pragma unroll 4
        for (int k = 0; k < m; k++) {
            int srcl = __shfl_sync(0xffffffffu, id, k);
            int ps = g_pos[s * NSUB + srcl];
            if (ps < 0) continue;
            float4 v = __ldg((const float4*)(hpool + (size_t)(s * KPOOL + ps) * F) + lane);
            acc.x += v.x; acc.y += v.y; acc.z += v.z; acc.w += v.w;
        }
    }
    int prow = s * KPOOL + pd;
    float d = g_dinv2[prow];
    float4 hv = __ldg((const float4*)(hpool + (size_t)prow * F) + lane);
    float4 bv = __ldg((const float4*)bsc + lane);
    float4 r;
    r.x = fmaxf((acc.x + hv.x) * d + bv.x, 0.f);
    r.y = fmaxf((acc.y + hv.y) * d + bv.y, 0.f);
    r.z = fmaxf((acc.z + hv.z) * d + bv.z, 0.f);
    r.w = fmaxf((acc.w + hv.w) * d + bv.w, 0.f);
    ((float4*)(xsub + (size_t)prow * F))[lane] = r;
}

// ---------------- emb2: add max/mean of xsub into subemb ----------------
__global__ void k_emb2(const float* __restrict__ xsub) {
    __shared__ float smx[512], ssm[512];
    int s = blockIdx.x, t = threadIdx.x;   // 512
    int col = t & 127, grp = t >> 7;
    const float* xs = xsub + (size_t)s * KPOOL * F + col;
    float mx = -INFINITY, sm = 0.f;
    for (int j = grp; j < KPOOL; j += 4) {
        float v = xs[(size_t)j * F]; mx = fmaxf(mx, v); sm += v;
    }
    smx[t] = mx; ssm[t] = sm;
    __syncthreads();
    if (grp == 0) {
        #pragma unroll
        for (int p = 1; p < 4; p++) {
            mx = fmaxf(mx, smx[p * 128 + col]); sm += ssm[p * 128 + col];
        }
        g_subemb[s * 256 + col]       += mx;
        g_subemb[s * 256 + 128 + col] += sm * (1.f / KPOOL);
    }
}

// ---------------- fused attention (seq_len=1 collapses to v @ Wo + bo) ----------------
__global__ void k_att(const float* __restrict__ Wqkv, const float* __restrict__ bqkv,
                      const float* __restrict__ Wo, const float* __restrict__ bo) {
    __shared__ float xs[256], vs[256];
    int s = blockIdx.x, j = threadIdx.x;   // 256
    xs[j] = g_subemb[s * 256 + j];
    __syncthreads();
    float acc = bqkv[512 + j];
    for (int k = 0; k < 256; k++) acc += xs[k] * Wqkv[k * 768 + 512 + j];
    vs[j] = acc;
    __syncthreads();
    float a2 = bo[j];
    for (int k = 0; k < 256; k++) a2 += vs[k] * Wo[k * 256 + j];
    g_att[s * 256 + j] = a2;
}

// ---------------- gather combined rows -> global embedding (in out buffer) ----------------
__global__ void k_gather_emb(float* __restrict__ gemb) {
    int n = blockIdx.x;
    int c = threadIdx.x;      // 384
    int st = g_stX[n], cn = g_cntX[n];
    float acc = 0.f;
    for (int k = 0; k < cn; k++) {
        int row = g_adjX[st + k];
        int s = row >> 10;
        acc += (c < F) ? g_x2[(size_t)row * F + c] : g_att[s * 256 + (c - F)];
    }
    gemb[(size_t)n * 384 + c] = acc;
}

// ---------------- fused final GCN agg + log_softmax (hf pre-scaled) ----------------
__global__ void k_final(const float* __restrict__ hfs, const float* __restrict__ bf,
                        float* __restrict__ out) {
    int w = (blockIdx.x * blockDim.x + threadIdx.x) >> 5;
    int lane = threadIdx.x & 31;
    if (w >= NGLOB) return;
    int st = g_stG[w], cn = g_cntG[w];
    float a = 0.f, b = 0.f;
    for (int base = 0; base < cn; base += 32) {
        int id = (base + lane < cn) ? g_adjG[st + base + lane] : 0;
        int m = min(32, cn - base);
        #pragma unroll 4
        for (int k = 0; k < m; k++) {
            int src = __shfl_sync(0xffffffffu, id, k);
            a += __ldg(&hfs[(size_t)src * 64 + lane]);
            b += __ldg(&hfs[(size_t)src * 64 + 32 + lane]);
        }
    }
    float d = g_dinvf[w];
    a = (a + hfs[(size_t)w * 64 + lane])      * d + bf[lane];
    b = (b + hfs[(size_t)w * 64 + 32 + lane]) * d + bf[32 + lane];
    float m = fmaxf(a, b);
    #pragma unroll
    for (int o = 16; o; o >>= 1) m = fmaxf(m, __shfl_xor_sync(0xffffffffu, m, o));
    float ssum = expf(a - m) + expf(b - m);
    #pragma unroll
    for (int o = 16; o; o >>= 1) ssum += __shfl_xor_sync(0xffffffffu, ssum, o);
    float ls = m + logf(ssum);
    out[(size_t)w * 64 + lane]      = a - ls;
    out[(size_t)w * 64 + 32 + lane] = b - ls;
}

// ========================= host orchestration =========================
extern "C" void kernel_launch(void* const* d_in, const int* in_sizes, int n_in,
                              void* d_out, int out_size) {
    const float* sub_x = (const float*)d_in[0];
    const int*   sei   = (const int*)d_in[1];
    const int*   sorig = (const int*)d_in[2];
    const int*   eidx  = (const int*)d_in[3];
    const float* W1  = (const float*)d_in[4];
    const float* b1  = (const float*)d_in[5];
    const float* W2  = (const float*)d_in[6];
    const float* b2  = (const float*)d_in[7];
    const float* Wp  = (const float*)d_in[8];
    const float* bp  = (const float*)d_in[9];
    const float* Wsc = (const float*)d_in[10];
    const float* bsc = (const float*)d_in[11];
    const float* Wqkv= (const float*)d_in[12];
    const float* bqkv= (const float*)d_in[13];
    const float* Wo  = (const float*)d_in[14];
    const float* bo  = (const float*)d_in[15];
    const float* Wf  = (const float*)d_in[16];
    const float* bf  = (const float*)d_in[17];
    float* out = (float*)d_out;

    float *h, *x1, *x2, *hp, *score, *xpool, *hpool, *xsub, *hf;
    float *dinv, *dinv2, *dinvf;
    int *cntG, *cntX;
    cudaGetSymbolAddress((void**)&h, g_h);
    cudaGetSymbolAddress((void**)&x1, g_x1);
    cudaGetSymbolAddress((void**)&x2, g_x2);
    cudaGetSymbolAddress((void**)&hp, g_hp);
    cudaGetSymbolAddress((void**)&score, g_score);
    cudaGetSymbolAddress((void**)&xpool, g_xpool);
    cudaGetSymbolAddress((void**)&hpool, g_hpool);
    cudaGetSymbolAddress((void**)&xsub, g_xsub);
    cudaGetSymbolAddress((void**)&hf, g_hf);
    cudaGetSymbolAddress((void**)&dinv, g_dinv);
    cudaGetSymbolAddress((void**)&dinv2, g_dinv2);
    cudaGetSymbolAddress((void**)&dinvf, g_dinvf);
    cudaGetSymbolAddress((void**)&cntG, g_cntG);
    cudaGetSymbolAddress((void**)&cntX, g_cntX);

    float* gemb = out + (size_t)NGLOB * NCLS;

    cudaFuncSetAttribute(tgemm, cudaFuncAttributeMaxDynamicSharedMemorySize, TG_SMEM);

    const int T = 256;
    const int ROWS = S * NSUB;          // 65536

    // --- CSR builds ---
    k_csr_sub<<<S, 1024>>>(sei);
    k_zero2<<<NGLOB / T, T>>>(cntG, cntX, NGLOB);
    k_hist_both<<<(EGLOB + ROWS) / T, T>>>(eidx, sorig);
    k_scan_block2<<<128, 1024>>>();
    k_scan_top2<<<1, 64>>>();
    k_scan_add2<<<2 * NGLOB / T, T>>>();
    k_adj_both<<<(EGLOB + ROWS) / T, T>>>(eidx, sorig);

    // --- GCN1 (fused scorer dot) / GCN2, dinv pre-scaled in GEMM epilogue ---
    tgemm<<<dim3(2, ROWS / 128), 256, TG_SMEM>>>(sub_x, W1, h, ROWS, F, F, dinv);
    k_gcn_sub<true, true><<<ROWS * 32 / T, T>>>(h, b1, x1, Wp, hp);
    tgemm<<<dim3(2, ROWS / 128), 256, TG_SMEM>>>(x1, W2, h, ROWS, F, F, dinv);
    k_gcn_sub<true, false><<<ROWS * 32 / T, T>>>(h, b2, x2, nullptr, nullptr);

    // --- scorer + fused pooling (topk/gates/xpool/emb1/degrees) ---
    k_score_csr<<<ROWS / T, T>>>(hp, bp, score);
    k_pool<<<S, 512>>>(x1, xpool);

    // --- pooled GCN ---
    tgemm<<<dim3(2, (S * KPOOL) / 128), 256, TG_SMEM>>>(xpool, Wsc, hpool, S * KPOOL, F, F, dinv2);
    k_gcn_pool<<<ROWS * 32 / T, T>>>(hpool, bsc, xsub);
    k_emb2<<<S, 512>>>(xsub);

    // --- collapsed attention (both small GEMMs fused) ---
    k_att<<<S, 256>>>(Wqkv, bqkv, Wo, bo);

    // --- gather into global embedding (written straight into out) ---
    k_gather_emb<<<NGLOB, 384>>>(gemb);

    // --- final GCN + log_softmax ---
    tgemm<<<dim3(1, NGLOB / 128), 256, TG_SMEM>>>(gemb, Wf, hf, NGLOB, 384, 64, dinvf);
    k_final<<<ROWS * 32 / T, T>>>(hf, bf, out);
}